// round 6
// baseline (speedup 1.0000x reference)
#include <cuda_runtime.h>
#include <math.h>

#define N_TOK 768
#define D_MODEL 512
#define CZ 128
#define NH 16
#define DH 32
#define LN_EPS 1e-5f
#define PSW 776  // padded row width for P smem

// ---------------- scratch ----------------
__device__ float g_q[N_TOK * D_MODEL];
__device__ float g_k[N_TOK * D_MODEL];
__device__ float g_v[N_TOK * D_MODEL];
__device__ float g_g[N_TOK * D_MODEL];
__device__ float g_o[N_TOK * D_MODEL];
__device__ float g_logits[(size_t)NH * N_TOK * N_TOK];  // bias -> P (in place, per-block safe)
__device__ float g_A[NH * CZ];
__device__ float g_SA[NH];
__device__ float g_CB[NH];

__device__ __forceinline__ unsigned f2tf32(float x) {
    unsigned r;
    asm("cvt.rna.tf32.f32 %0, %1;" : "=r"(r) : "f"(x));
    return r;
}

__device__ __forceinline__ void split_tf32(float x, unsigned& hi, unsigned& lo) {
    hi = f2tf32(x);
    lo = f2tf32(x - __uint_as_float(hi));
}

__device__ __forceinline__ void mma_tf32(float* d,
                                         unsigned a0, unsigned a1, unsigned a2, unsigned a3,
                                         unsigned b0, unsigned b1) {
    asm volatile(
        "mma.sync.aligned.m16n8k8.row.col.f32.tf32.tf32.f32 "
        "{%0,%1,%2,%3}, {%4,%5,%6,%7}, {%8,%9}, {%0,%1,%2,%3};"
        : "+f"(d[0]), "+f"(d[1]), "+f"(d[2]), "+f"(d[3])
        : "r"(a0), "r"(a1), "r"(a2), "r"(a3), "r"(b0), "r"(b1));
}

// 3xTF32: d += a*b with near-fp32 precision
__device__ __forceinline__ void mma3(float* d, const unsigned* ah, const unsigned* al,
                                     unsigned bh0, unsigned bh1, unsigned bl0, unsigned bl1) {
    mma_tf32(d, ah[0], ah[1], ah[2], ah[3], bh0, bh1);
    mma_tf32(d, ah[0], ah[1], ah[2], ah[3], bl0, bl1);
    mma_tf32(d, al[0], al[1], al[2], al[3], bh0, bh1);
}

// ---------------- K0: fold LN affine into Wz ----------------
__global__ void prep_kernel(const float* __restrict__ Wz,
                            const float* __restrict__ lnw,
                            const float* __restrict__ lnb) {
    __shared__ float red[8];
    int c = threadIdx.x;  // 128 threads
    float wc = lnw[c], bc = lnb[c];
    for (int h = 0; h < NH; h++) {
        float wz = Wz[h * CZ + c];
        float a = wz * wc;
        g_A[h * CZ + c] = a;
        float sa = a, cb = wz * bc;
        for (int o = 16; o; o >>= 1) {
            sa += __shfl_down_sync(0xffffffffu, sa, o);
            cb += __shfl_down_sync(0xffffffffu, cb, o);
        }
        if ((c & 31) == 0) { red[c >> 5] = sa; red[4 + (c >> 5)] = cb; }
        __syncthreads();
        if (c == 0) {
            g_SA[h] = red[0] + red[1] + red[2] + red[3];
            g_CB[h] = red[4] + red[5] + red[6] + red[7];
        }
        __syncthreads();
    }
}

// ---------------- K1: q,k,v,g projections via 3xTF32 MMA ----------------
__global__ void proj_kernel(const float* __restrict__ s,
                            const float* __restrict__ Wq, const float* __restrict__ bq,
                            const float* __restrict__ Wk, const float* __restrict__ Wv,
                            const float* __restrict__ Wg) {
    __shared__ float ss[128][20];
    __shared__ float ws[64][20];
    int w = blockIdx.z;
    const float* W = (w == 0) ? Wq : (w == 1) ? Wk : (w == 2) ? Wv : Wg;
    float* C = (w == 0) ? g_q : (w == 1) ? g_k : (w == 2) ? g_v : g_g;
    int bm = blockIdx.y * 128, bn = blockIdx.x * 64;
    int tid = threadIdx.x;
    int wid = tid >> 5, lane = tid & 31;
    int mtile = wid & 3, ntile = wid >> 2;
    int gr = lane >> 2, tig = lane & 3;
    float acc[2][4][4] = {};

    for (int k0 = 0; k0 < D_MODEL; k0 += 16) {
#pragma unroll
        for (int it = 0; it < 2; it++) {
            int e = tid + it * 256;
            int r = e >> 2, c4 = (e & 3) * 4;
            float4 v = *reinterpret_cast<const float4*>(&s[(bm + r) * D_MODEL + k0 + c4]);
            *reinterpret_cast<float4*>(&ss[r][c4]) = v;
        }
        {
            int r = tid >> 2, c4 = (tid & 3) * 4;
            float4 v = *reinterpret_cast<const float4*>(&W[(bn + r) * D_MODEL + k0 + c4]);
            *reinterpret_cast<float4*>(&ws[r][c4]) = v;
        }
        __syncthreads();
#pragma unroll
        for (int kk = 0; kk < 16; kk += 8) {
            unsigned ah[2][4], al[2][4];
#pragma unroll
            for (int mi = 0; mi < 2; mi++) {
                int mr = mtile * 32 + mi * 16 + gr;
                split_tf32(ss[mr][kk + tig], ah[mi][0], al[mi][0]);
                split_tf32(ss[mr + 8][kk + tig], ah[mi][1], al[mi][1]);
                split_tf32(ss[mr][kk + tig + 4], ah[mi][2], al[mi][2]);
                split_tf32(ss[mr + 8][kk + tig + 4], ah[mi][3], al[mi][3]);
            }
#pragma unroll
            for (int ni = 0; ni < 4; ni++) {
                int nr = ntile * 32 + ni * 8 + gr;
                unsigned bh0, bl0, bh1, bl1;
                split_tf32(ws[nr][kk + tig], bh0, bl0);
                split_tf32(ws[nr][kk + tig + 4], bh1, bl1);
#pragma unroll
                for (int mi = 0; mi < 2; mi++)
                    mma3(acc[mi][ni], ah[mi], al[mi], bh0, bh1, bl0, bl1);
            }
        }
        __syncthreads();
    }
#pragma unroll
    for (int mi = 0; mi < 2; mi++) {
#pragma unroll
        for (int ni = 0; ni < 4; ni++) {
            int m = bm + mtile * 32 + mi * 16 + gr;
            int n = bn + ntile * 32 + ni * 8 + 2 * tig;
            float b0 = 0.f, b1 = 0.f;
            if (w == 0) { b0 = bq[n]; b1 = bq[n + 1]; }
            *reinterpret_cast<float2*>(&C[m * D_MODEL + n]) =
                make_float2(acc[mi][ni][0] + b0, acc[mi][ni][1] + b1);
            *reinterpret_cast<float2*>(&C[(m + 8) * D_MODEL + n]) =
                make_float2(acc[mi][ni][2] + b0, acc[mi][ni][3] + b1);
        }
    }
}

// ---------------- K2: pair bias via tf32 MMA + LN linearity (1x tf32) ----------------
__global__ void bias_kernel(const float* __restrict__ z) {
    __shared__ float zs[64][132];
    __shared__ float As[16][132];
    __shared__ float mu_s[64], rs_s[64];
    int i = blockIdx.y;
    int j0 = blockIdx.x * 64;
    int tid = threadIdx.x;

    for (int e = tid; e < 16 * 32; e += 256) {
        int h = e >> 5, c4 = (e & 31) * 4;
        float4 v = *reinterpret_cast<const float4*>(&g_A[h * CZ + c4]);
        *reinterpret_cast<float4*>(&As[h][c4]) = v;
    }
    const float* zb = z + ((size_t)i * N_TOK + j0) * CZ;
#pragma unroll
    for (int it = 0; it < 8; it++) {
        int f4 = tid + it * 256;
        int r = f4 >> 5, c4 = f4 & 31;
        float4 v = *reinterpret_cast<const float4*>(zb + r * CZ + c4 * 4);
        *reinterpret_cast<float4*>(&zs[r][c4 * 4]) = v;
    }
    __syncthreads();

    {
        int row = tid >> 2, sub = tid & 3;
        float sm = 0.f, sq = 0.f;
#pragma unroll
        for (int c4 = 0; c4 < 8; c4++) {
            float4 v = *reinterpret_cast<float4*>(&zs[row][(sub * 8 + c4) * 4]);
            sm += v.x + v.y + v.z + v.w;
            sq += v.x * v.x + v.y * v.y + v.z * v.z + v.w * v.w;
        }
        sm += __shfl_xor_sync(0xffffffffu, sm, 1);
        sm += __shfl_xor_sync(0xffffffffu, sm, 2);
        sq += __shfl_xor_sync(0xffffffffu, sq, 1);
        sq += __shfl_xor_sync(0xffffffffu, sq, 2);
        if (sub == 0) {
            float m = sm * (1.0f / CZ);
            float var = sq * (1.0f / CZ) - m * m;
            mu_s[row] = m;
            rs_s[row] = rsqrtf(var + LN_EPS);
        }
    }
    __syncthreads();

    int w = tid >> 5, lane = tid & 31;
    int mtile = w & 3, ntile = w >> 2;
    int gr = lane >> 2, tig = lane & 3;

    const float* zr0 = &zs[mtile * 16 + gr][0];
    const float* zr1 = &zs[mtile * 16 + gr + 8][0];
    const float* ar = &As[ntile * 8 + gr][0];

    float d[4] = {};
#pragma unroll
    for (int k0 = 0; k0 < CZ; k0 += 8) {
        unsigned a0 = f2tf32(zr0[k0 + tig]);
        unsigned a1 = f2tf32(zr1[k0 + tig]);
        unsigned a2 = f2tf32(zr0[k0 + tig + 4]);
        unsigned a3 = f2tf32(zr1[k0 + tig + 4]);
        unsigned b0 = f2tf32(ar[k0 + tig]);
        unsigned b1 = f2tf32(ar[k0 + tig + 4]);
        mma_tf32(d, a0, a1, a2, a3, b0, b1);
    }

    int jl = mtile * 16 + gr;
    int jh = jl + 8;
    int h0 = ntile * 8 + 2 * tig, h1 = h0 + 1;
    float mu_l = mu_s[jl], rs_l = rs_s[jl];
    float mu_h = mu_s[jh], rs_h = rs_s[jh];
    float sa0 = g_SA[h0], cb0 = g_CB[h0];
    float sa1 = g_SA[h1], cb1 = g_CB[h1];
    g_logits[((size_t)h0 * N_TOK + i) * N_TOK + j0 + jl] = rs_l * (d[0] - mu_l * sa0) + cb0;
    g_logits[((size_t)h1 * N_TOK + i) * N_TOK + j0 + jl] = rs_l * (d[1] - mu_l * sa1) + cb1;
    g_logits[((size_t)h0 * N_TOK + i) * N_TOK + j0 + jh] = rs_h * (d[2] - mu_h * sa0) + cb0;
    g_logits[((size_t)h1 * N_TOK + i) * N_TOK + j0 + jh] = rs_h * (d[3] - mu_h * sa1) + cb1;
}

// ---------------- K3: fused logits + bias + softmax -> P (in-place over bias) ----------------
// block = (16 q-rows, head), 256 thr = 8 warps. Warp w owns j-columns w*8 per 64-j tile.
// 3xTF32 QK. P row (16 x 768) lives in smem; softmax at end; writes P over bias.
__global__ void attn_kernel() {
    extern __shared__ float sm_[];
    float* qs = sm_;                    // [16][40]
    float* ks = qs + 16 * 40;           // [64][40]
    float* Ps = ks + 64 * 40;           // [16][PSW]
    int h = blockIdx.y;
    int i0 = blockIdx.x * 16;
    int tid = threadIdx.x;
    int wid = tid >> 5, lane = tid & 31;
    int gr = lane >> 2, tig = lane & 3;
    const float scale = 0.17677669529663687f;

    if (tid < 128) {
        int r = tid >> 3, c4 = (tid & 7) * 4;
        float4 q = *reinterpret_cast<const float4*>(&g_q[(i0 + r) * D_MODEL + h * DH + c4]);
        q.x *= scale; q.y *= scale; q.z *= scale; q.w *= scale;
        *reinterpret_cast<float4*>(&qs[r * 40 + c4]) = q;
    }
    __syncthreads();

    // hoist q fragments (A side), split once
    unsigned qa_h[4][4], qa_l[4][4];
#pragma unroll
    for (int kk4 = 0; kk4 < 4; kk4++) {
        int k = kk4 * 8;
        split_tf32(qs[gr * 40 + k + tig], qa_h[kk4][0], qa_l[kk4][0]);
        split_tf32(qs[(gr + 8) * 40 + k + tig], qa_h[kk4][1], qa_l[kk4][1]);
        split_tf32(qs[gr * 40 + k + tig + 4], qa_h[kk4][2], qa_l[kk4][2]);
        split_tf32(qs[(gr + 8) * 40 + k + tig + 4], qa_h[kk4][3], qa_l[kk4][3]);
    }

    for (int j0 = 0; j0 < N_TOK; j0 += 64) {
#pragma unroll
        for (int it = 0; it < 2; it++) {
            int e = tid + it * 256;
            int r = e >> 3, c4 = (e & 7) * 4;
            float4 k4 = *reinterpret_cast<const float4*>(
                &g_k[(j0 + r) * D_MODEL + h * DH + c4]);
            *reinterpret_cast<float4*>(&ks[r * 40 + c4]) = k4;
        }
        __syncthreads();

        float acc[4] = {};
        int nr = wid * 8 + gr;
#pragma unroll
        for (int kk4 = 0; kk4 < 4; kk4++) {
            int k = kk4 * 8;
            unsigned bh0, bl0, bh1, bl1;
            split_tf32(ks[nr * 40 + k + tig], bh0, bl0);
            split_tf32(ks[nr * 40 + k + tig + 4], bh1, bl1);
            mma3(acc, qa_h[kk4], qa_l[kk4], bh0, bh1, bl0, bl1);
        }
        // epilogue: add bias (gmem) and park in Ps
        int jc = j0 + wid * 8 + 2 * tig;
        float2 b0 = *reinterpret_cast<const float2*>(
            &g_logits[((size_t)h * N_TOK + i0 + gr) * N_TOK + jc]);
        float2 b1 = *reinterpret_cast<const float2*>(
            &g_logits[((size_t)h * N_TOK + i0 + gr + 8) * N_TOK + jc]);
        Ps[gr * PSW + jc] = acc[0] + b0.x;
        Ps[gr * PSW + jc + 1] = acc[1] + b0.y;
        Ps[(gr + 8) * PSW + jc] = acc[2] + b1.x;
        Ps[(gr + 8) * PSW + jc + 1] = acc[3] + b1.y;
        __syncthreads();
    }

    // softmax: warp w handles rows 2w, 2w+1
#pragma unroll
    for (int rr = 0; rr < 2; rr++) {
        int r = wid * 2 + rr;
        float v[24];
        float mx = -1e30f;
#pragma unroll
        for (int t = 0; t < 24; t++) {
            v[t] = Ps[r * PSW + lane + 32 * t];
            mx = fmaxf(mx, v[t]);
        }
#pragma unroll
        for (int o = 16; o; o >>= 1) mx = fmaxf(mx, __shfl_xor_sync(0xffffffffu, mx, o));
        float sum = 0.f;
#pragma unroll
        for (int t = 0; t < 24; t++) { v[t] = __expf(v[t] - mx); sum += v[t]; }
#pragma unroll
        for (int o = 16; o; o >>= 1) sum += __shfl_xor_sync(0xffffffffu, sum, o);
        float inv = 1.0f / sum;
        float* dst = &g_logits[((size_t)h * N_TOK + i0 + r) * N_TOK];
#pragma unroll
        for (int t = 0; t < 24; t++) dst[lane + 32 * t] = v[t] * inv;
    }
}

// ---------------- K3c: O = P @ V (3xTF32 MMA) ----------------
__global__ void attnv_kernel() {
    __shared__ float ps[64][68];
    __shared__ float vs[32][68];
    int h = blockIdx.y;
    int i0 = blockIdx.x * 64;
    int tid = threadIdx.x;
    int wid = tid >> 5, lane = tid & 31;
    int mtile = wid & 3, ntile = wid >> 2;
    int gr = lane >> 2, tig = lane & 3;
    float acc[2][4] = {};

    for (int j0 = 0; j0 < N_TOK; j0 += 64) {
#pragma unroll
        for (int it = 0; it < 4; it++) {
            int e = tid + it * 256;
            int r = e >> 4, c4 = (e & 15) * 4;
            float4 v = *reinterpret_cast<const float4*>(
                &g_logits[((size_t)h * N_TOK + i0 + r) * N_TOK + j0 + c4]);
            *reinterpret_cast<float4*>(&ps[r][c4]) = v;
        }
#pragma unroll
        for (int it = 0; it < 8; it++) {
            int e = tid + it * 256;
            int r = e >> 5, d = e & 31;
            vs[d][r] = g_v[(j0 + r) * D_MODEL + h * DH + d];
        }
        __syncthreads();
#pragma unroll
        for (int kk = 0; kk < 64; kk += 8) {
            int mr = mtile * 16 + gr;
            unsigned ah[4], al[4];
            split_tf32(ps[mr][kk + tig], ah[0], al[0]);
            split_tf32(ps[mr + 8][kk + tig], ah[1], al[1]);
            split_tf32(ps[mr][kk + tig + 4], ah[2], al[2]);
            split_tf32(ps[mr + 8][kk + tig + 4], ah[3], al[3]);
#pragma unroll
            for (int ni = 0; ni < 2; ni++) {
                int nr = ntile * 16 + ni * 8 + gr;
                unsigned bh0, bl0, bh1, bl1;
                split_tf32(vs[nr][kk + tig], bh0, bl0);
                split_tf32(vs[nr][kk + tig + 4], bh1, bl1);
                mma3(acc[ni], ah, al, bh0, bh1, bl0, bl1);
            }
        }
        __syncthreads();
    }
#pragma unroll
    for (int ni = 0; ni < 2; ni++) {
        int m = i0 + mtile * 16 + gr;
        int d = ntile * 16 + ni * 8 + 2 * tig;
        *reinterpret_cast<float2*>(&g_o[m * D_MODEL + h * DH + d]) =
            make_float2(acc[ni][0], acc[ni][1]);
        *reinterpret_cast<float2*>(&g_o[(m + 8) * D_MODEL + h * DH + d]) =
            make_float2(acc[ni][2], acc[ni][3]);
    }
}

// ---------------- K4: out = (o * sigmoid(g)) @ Wo^T (3xTF32 MMA) ----------------
__global__ void out_kernel(const float* __restrict__ Wo, float* __restrict__ out) {
    __shared__ float ss[128][20];
    __shared__ float ws[64][20];
    int bm = blockIdx.y * 128, bn = blockIdx.x * 64;
    int tid = threadIdx.x;
    int wid = tid >> 5, lane = tid & 31;
    int mtile = wid & 3, ntile = wid >> 2;
    int gr = lane >> 2, tig = lane & 3;
    float acc[2][4][4] = {};

    for (int k0 = 0; k0 < D_MODEL; k0 += 16) {
#pragma unroll
        for (int it = 0; it < 2; it++) {
            int e = tid + it * 256;
            int r = e >> 2, c4 = (e & 3) * 4;
            float4 va = *reinterpret_cast<const float4*>(&g_o[(bm + r) * D_MODEL + k0 + c4]);
            float4 vg = *reinterpret_cast<const float4*>(&g_g[(bm + r) * D_MODEL + k0 + c4]);
            va.x *= 1.0f / (1.0f + __expf(-vg.x));
            va.y *= 1.0f / (1.0f + __expf(-vg.y));
            va.z *= 1.0f / (1.0f + __expf(-vg.z));
            va.w *= 1.0f / (1.0f + __expf(-vg.w));
            *reinterpret_cast<float4*>(&ss[r][c4]) = va;
        }
        {
            int r = tid >> 2, c4 = (tid & 3) * 4;
            float4 v = *reinterpret_cast<const float4*>(&Wo[(bn + r) * D_MODEL + k0 + c4]);
            *reinterpret_cast<float4*>(&ws[r][c4]) = v;
        }
        __syncthreads();
#pragma unroll
        for (int kk = 0; kk < 16; kk += 8) {
            unsigned ah[2][4], al[2][4];
#pragma unroll
            for (int mi = 0; mi < 2; mi++) {
                int mr = mtile * 32 + mi * 16 + gr;
                split_tf32(ss[mr][kk + tig], ah[mi][0], al[mi][0]);
                split_tf32(ss[mr + 8][kk + tig], ah[mi][1], al[mi][1]);
                split_tf32(ss[mr][kk + tig + 4], ah[mi][2], al[mi][2]);
                split_tf32(ss[mr + 8][kk + tig + 4], ah[mi][3], al[mi][3]);
            }
#pragma unroll
            for (int ni = 0; ni < 4; ni++) {
                int nr = ntile * 32 + ni * 8 + gr;
                unsigned bh0, bl0, bh1, bl1;
                split_tf32(ws[nr][kk + tig], bh0, bl0);
                split_tf32(ws[nr][kk + tig + 4], bh1, bl1);
#pragma unroll
                for (int mi = 0; mi < 2; mi++)
                    mma3(acc[mi][ni], ah[mi], al[mi], bh0, bh1, bl0, bl1);
            }
        }
        __syncthreads();
    }
#pragma unroll
    for (int mi = 0; mi < 2; mi++) {
#pragma unroll
        for (int ni = 0; ni < 4; ni++) {
            int m = bm + mtile * 32 + mi * 16 + gr;
            int n = bn + ntile * 32 + ni * 8 + 2 * tig;
            *reinterpret_cast<float2*>(&out[m * D_MODEL + n]) =
                make_float2(acc[mi][ni][0], acc[mi][ni][1]);
            *reinterpret_cast<float2*>(&out[(m + 8) * D_MODEL + n]) =
                make_float2(acc[mi][ni][2], acc[mi][ni][3]);
        }
    }
}

// ---------------- launch ----------------
extern "C" void kernel_launch(void* const* d_in, const int* in_sizes, int n_in,
                              void* d_out, int out_size) {
    const float* s   = (const float*)d_in[0];
    const float* z   = (const float*)d_in[1];
    const float* Wq  = (const float*)d_in[2];
    const float* bq  = (const float*)d_in[3];
    const float* Wk  = (const float*)d_in[4];
    const float* Wv  = (const float*)d_in[5];
    const float* Wg  = (const float*)d_in[6];
    const float* Wo  = (const float*)d_in[7];
    const float* lnw = (const float*)d_in[8];
    const float* lnb = (const float*)d_in[9];
    const float* Wz  = (const float*)d_in[10];
    float* out = (float*)d_out;

    const int attn_smem = (16 * 40 + 64 * 40 + 16 * PSW) * 4;
    cudaFuncSetAttribute(attn_kernel, cudaFuncAttributeMaxDynamicSharedMemorySize, attn_smem);

    prep_kernel<<<1, 128>>>(Wz, lnw, lnb);
    proj_kernel<<<dim3(D_MODEL / 64, N_TOK / 128, 4), 256>>>(s, Wq, bq, Wk, Wv, Wg);
    bias_kernel<<<dim3(N_TOK / 64, N_TOK), 256>>>(z);
    attn_kernel<<<dim3(N_TOK / 16, NH), 256, attn_smem>>>();
    attnv_kernel<<<dim3(N_TOK / 64, NH), 256>>>();
    out_kernel<<<dim3(D_MODEL / 64, N_TOK / 128), 256>>>(Wo, out);
}

// round 7
// speedup vs baseline: 1.0241x; 1.0241x over previous
#include <cuda_runtime.h>
#include <math.h>

#define N_TOK 768
#define D_MODEL 512
#define CZ 128
#define NH 16
#define DH 32
#define LN_EPS 1e-5f
#define PSW 776  // padded row width for P smem
#define BIAS_ITILES 8

// ---------------- scratch ----------------
__device__ float g_q[N_TOK * D_MODEL];
__device__ float g_k[N_TOK * D_MODEL];
__device__ float g_v[N_TOK * D_MODEL];
__device__ float g_g[N_TOK * D_MODEL];
__device__ float g_o[N_TOK * D_MODEL];
__device__ float g_logits[(size_t)NH * N_TOK * N_TOK];  // bias -> P (in place, per-block safe)
__device__ float g_A[NH * CZ];
__device__ float g_SA[NH];
__device__ float g_CB[NH];

__device__ __forceinline__ unsigned f2tf32(float x) {
    unsigned r;
    asm("cvt.rna.tf32.f32 %0, %1;" : "=r"(r) : "f"(x));
    return r;
}

__device__ __forceinline__ void split_tf32(float x, unsigned& hi, unsigned& lo) {
    hi = f2tf32(x);
    lo = f2tf32(x - __uint_as_float(hi));
}

__device__ __forceinline__ void mma_tf32(float* d,
                                         unsigned a0, unsigned a1, unsigned a2, unsigned a3,
                                         unsigned b0, unsigned b1) {
    asm volatile(
        "mma.sync.aligned.m16n8k8.row.col.f32.tf32.tf32.f32 "
        "{%0,%1,%2,%3}, {%4,%5,%6,%7}, {%8,%9}, {%0,%1,%2,%3};"
        : "+f"(d[0]), "+f"(d[1]), "+f"(d[2]), "+f"(d[3])
        : "r"(a0), "r"(a1), "r"(a2), "r"(a3), "r"(b0), "r"(b1));
}

__device__ __forceinline__ void mma3(float* d, const unsigned* ah, const unsigned* al,
                                     unsigned bh0, unsigned bh1, unsigned bl0, unsigned bl1) {
    mma_tf32(d, ah[0], ah[1], ah[2], ah[3], bh0, bh1);
    mma_tf32(d, ah[0], ah[1], ah[2], ah[3], bl0, bl1);
    mma_tf32(d, al[0], al[1], al[2], al[3], bh0, bh1);
}

__device__ __forceinline__ void cp_async16(unsigned dst, const void* src) {
    asm volatile("cp.async.cg.shared.global [%0], [%1], 16;" :: "r"(dst), "l"(src));
}

// ---------------- K0: fold LN affine into Wz ----------------
__global__ void prep_kernel(const float* __restrict__ Wz,
                            const float* __restrict__ lnw,
                            const float* __restrict__ lnb) {
    __shared__ float red[8];
    int c = threadIdx.x;  // 128 threads
    float wc = lnw[c], bc = lnb[c];
    for (int h = 0; h < NH; h++) {
        float wz = Wz[h * CZ + c];
        float a = wz * wc;
        g_A[h * CZ + c] = a;
        float sa = a, cb = wz * bc;
        for (int o = 16; o; o >>= 1) {
            sa += __shfl_down_sync(0xffffffffu, sa, o);
            cb += __shfl_down_sync(0xffffffffu, cb, o);
        }
        if ((c & 31) == 0) { red[c >> 5] = sa; red[4 + (c >> 5)] = cb; }
        __syncthreads();
        if (c == 0) {
            g_SA[h] = red[0] + red[1] + red[2] + red[3];
            g_CB[h] = red[4] + red[5] + red[6] + red[7];
        }
        __syncthreads();
    }
}

// ---------------- K1: q,k,v,g projections via 3xTF32 MMA ----------------
__global__ void proj_kernel(const float* __restrict__ s,
                            const float* __restrict__ Wq, const float* __restrict__ bq,
                            const float* __restrict__ Wk, const float* __restrict__ Wv,
                            const float* __restrict__ Wg) {
    __shared__ float ss[128][20];
    __shared__ float ws[64][20];
    int w = blockIdx.z;
    const float* W = (w == 0) ? Wq : (w == 1) ? Wk : (w == 2) ? Wv : Wg;
    float* C = (w == 0) ? g_q : (w == 1) ? g_k : (w == 2) ? g_v : g_g;
    int bm = blockIdx.y * 128, bn = blockIdx.x * 64;
    int tid = threadIdx.x;
    int wid = tid >> 5, lane = tid & 31;
    int mtile = wid & 3, ntile = wid >> 2;
    int gr = lane >> 2, tig = lane & 3;
    float acc[2][4][4] = {};

    for (int k0 = 0; k0 < D_MODEL; k0 += 16) {
#pragma unroll
        for (int it = 0; it < 2; it++) {
            int e = tid + it * 256;
            int r = e >> 2, c4 = (e & 3) * 4;
            float4 v = *reinterpret_cast<const float4*>(&s[(bm + r) * D_MODEL + k0 + c4]);
            *reinterpret_cast<float4*>(&ss[r][c4]) = v;
        }
        {
            int r = tid >> 2, c4 = (tid & 3) * 4;
            float4 v = *reinterpret_cast<const float4*>(&W[(bn + r) * D_MODEL + k0 + c4]);
            *reinterpret_cast<float4*>(&ws[r][c4]) = v;
        }
        __syncthreads();
#pragma unroll
        for (int kk = 0; kk < 16; kk += 8) {
            unsigned ah[2][4], al[2][4];
#pragma unroll
            for (int mi = 0; mi < 2; mi++) {
                int mr = mtile * 32 + mi * 16 + gr;
                split_tf32(ss[mr][kk + tig], ah[mi][0], al[mi][0]);
                split_tf32(ss[mr + 8][kk + tig], ah[mi][1], al[mi][1]);
                split_tf32(ss[mr][kk + tig + 4], ah[mi][2], al[mi][2]);
                split_tf32(ss[mr + 8][kk + tig + 4], ah[mi][3], al[mi][3]);
            }
#pragma unroll
            for (int ni = 0; ni < 4; ni++) {
                int nr = ntile * 32 + ni * 8 + gr;
                unsigned bh0, bl0, bh1, bl1;
                split_tf32(ws[nr][kk + tig], bh0, bl0);
                split_tf32(ws[nr][kk + tig + 4], bh1, bl1);
#pragma unroll
                for (int mi = 0; mi < 2; mi++)
                    mma3(acc[mi][ni], ah[mi], al[mi], bh0, bh1, bl0, bl1);
            }
        }
        __syncthreads();
    }
#pragma unroll
    for (int mi = 0; mi < 2; mi++) {
#pragma unroll
        for (int ni = 0; ni < 4; ni++) {
            int m = bm + mtile * 32 + mi * 16 + gr;
            int n = bn + ntile * 32 + ni * 8 + 2 * tig;
            float b0 = 0.f, b1 = 0.f;
            if (w == 0) { b0 = bq[n]; b1 = bq[n + 1]; }
            *reinterpret_cast<float2*>(&C[m * D_MODEL + n]) =
                make_float2(acc[mi][ni][0] + b0, acc[mi][ni][1] + b1);
            *reinterpret_cast<float2*>(&C[(m + 8) * D_MODEL + n]) =
                make_float2(acc[mi][ni][2] + b0, acc[mi][ni][3] + b1);
        }
    }
}

// ---------------- K2: pair bias, double-buffered cp.async pipeline ----------------
// block = (j-tile 64, i-group of 8). Prefetch z tile i+1 while computing tile i.
__global__ void bias_kernel(const float* __restrict__ z) {
    extern __shared__ float bsm[];
    float* zbuf[2] = {bsm, bsm + 64 * 132};
    float* As = bsm + 2 * 64 * 132;     // [16][132]
    float* mu_s = As + 16 * 132;        // [64]
    float* rs_s = mu_s + 64;            // [64]
    int j0 = blockIdx.x * 64;
    int ibase = blockIdx.y * BIAS_ITILES;
    int tid = threadIdx.x;

    // load A once (ordered by first __syncthreads below)
    for (int e = tid; e < 16 * 32; e += 256) {
        int h = e >> 5, c4 = (e & 31) * 4;
        float4 v = *reinterpret_cast<const float4*>(&g_A[h * CZ + c4]);
        *reinterpret_cast<float4*>(&As[h * 132 + c4]) = v;
    }

    int ldr = tid >> 5, ldc = tid & 31;  // 32 rows-groups? no: r = f4>>5 below

    // issue tile 0
    {
        const float* zb = z + ((size_t)ibase * N_TOK + j0) * CZ;
        unsigned dst = (unsigned)__cvta_generic_to_shared(zbuf[0]);
#pragma unroll
        for (int it = 0; it < 8; it++) {
            int f4 = tid + it * 256;
            int r = f4 >> 5, c4 = f4 & 31;
            cp_async16(dst + (r * 132 + c4 * 4) * 4, zb + r * CZ + c4 * 4);
        }
        asm volatile("cp.async.commit_group;");
    }

    int w = tid >> 5, lane = tid & 31;
    int mtile = w & 3, ntile = w >> 2;
    int gr = lane >> 2, tig = lane & 3;

    for (int t = 0; t < BIAS_ITILES; t++) {
        float* cur = zbuf[t & 1];
        if (t + 1 < BIAS_ITILES) {
            const float* zb = z + ((size_t)(ibase + t + 1) * N_TOK + j0) * CZ;
            unsigned dst = (unsigned)__cvta_generic_to_shared(zbuf[(t + 1) & 1]);
#pragma unroll
            for (int it = 0; it < 8; it++) {
                int f4 = tid + it * 256;
                int r = f4 >> 5, c4 = f4 & 31;
                cp_async16(dst + (r * 132 + c4 * 4) * 4, zb + r * CZ + c4 * 4);
            }
            asm volatile("cp.async.commit_group;");
            asm volatile("cp.async.wait_group 1;");
        } else {
            asm volatile("cp.async.wait_group 0;");
        }
        __syncthreads();

        // stats: 4 threads per row, quad reduce
        {
            int row = tid >> 2, sub = tid & 3;
            float sm = 0.f, sq = 0.f;
#pragma unroll
            for (int c4 = 0; c4 < 8; c4++) {
                float4 v = *reinterpret_cast<float4*>(&cur[row * 132 + (sub * 8 + c4) * 4]);
                sm += v.x + v.y + v.z + v.w;
                sq += v.x * v.x + v.y * v.y + v.z * v.z + v.w * v.w;
            }
            sm += __shfl_xor_sync(0xffffffffu, sm, 1);
            sm += __shfl_xor_sync(0xffffffffu, sm, 2);
            sq += __shfl_xor_sync(0xffffffffu, sq, 1);
            sq += __shfl_xor_sync(0xffffffffu, sq, 2);
            if (sub == 0) {
                float m = sm * (1.0f / CZ);
                float var = sq * (1.0f / CZ) - m * m;
                mu_s[row] = m;
                rs_s[row] = rsqrtf(var + LN_EPS);
            }
        }
        __syncthreads();

        const float* zr0 = &cur[(mtile * 16 + gr) * 132];
        const float* zr1 = &cur[(mtile * 16 + gr + 8) * 132];
        const float* ar = &As[(ntile * 8 + gr) * 132];

        float d[4] = {};
#pragma unroll
        for (int k0 = 0; k0 < CZ; k0 += 8) {
            unsigned a0 = f2tf32(zr0[k0 + tig]);
            unsigned a1 = f2tf32(zr1[k0 + tig]);
            unsigned a2 = f2tf32(zr0[k0 + tig + 4]);
            unsigned a3 = f2tf32(zr1[k0 + tig + 4]);
            unsigned b0 = f2tf32(ar[k0 + tig]);
            unsigned b1 = f2tf32(ar[k0 + tig + 4]);
            mma_tf32(d, a0, a1, a2, a3, b0, b1);
        }

        int i = ibase + t;
        int jl = mtile * 16 + gr;
        int jh = jl + 8;
        int h0 = ntile * 8 + 2 * tig, h1 = h0 + 1;
        float mu_l = mu_s[jl], rs_l = rs_s[jl];
        float mu_h = mu_s[jh], rs_h = rs_s[jh];
        float sa0 = g_SA[h0], cb0 = g_CB[h0];
        float sa1 = g_SA[h1], cb1 = g_CB[h1];
        g_logits[((size_t)h0 * N_TOK + i) * N_TOK + j0 + jl] = rs_l * (d[0] - mu_l * sa0) + cb0;
        g_logits[((size_t)h1 * N_TOK + i) * N_TOK + j0 + jl] = rs_l * (d[1] - mu_l * sa1) + cb1;
        g_logits[((size_t)h0 * N_TOK + i) * N_TOK + j0 + jh] = rs_h * (d[2] - mu_h * sa0) + cb0;
        g_logits[((size_t)h1 * N_TOK + i) * N_TOK + j0 + jh] = rs_h * (d[3] - mu_h * sa1) + cb1;
        __syncthreads();  // all reads of cur done before it is refilled next iter
    }
}

// ---------------- K3: fused logits + bias + softmax -> P (in-place over bias) ----------------
__global__ void attn_kernel() {
    extern __shared__ float sm_[];
    float* qs = sm_;                    // [16][40]
    float* ks = qs + 16 * 40;           // [64][40]
    float* Ps = ks + 64 * 40;           // [16][PSW]
    int h = blockIdx.y;
    int i0 = blockIdx.x * 16;
    int tid = threadIdx.x;
    int wid = tid >> 5, lane = tid & 31;
    int gr = lane >> 2, tig = lane & 3;
    const float scale = 0.17677669529663687f;

    if (tid < 128) {
        int r = tid >> 3, c4 = (tid & 7) * 4;
        float4 q = *reinterpret_cast<const float4*>(&g_q[(i0 + r) * D_MODEL + h * DH + c4]);
        q.x *= scale; q.y *= scale; q.z *= scale; q.w *= scale;
        *reinterpret_cast<float4*>(&qs[r * 40 + c4]) = q;
    }
    __syncthreads();

    unsigned qa_h[4][4], qa_l[4][4];
#pragma unroll
    for (int kk4 = 0; kk4 < 4; kk4++) {
        int k = kk4 * 8;
        split_tf32(qs[gr * 40 + k + tig], qa_h[kk4][0], qa_l[kk4][0]);
        split_tf32(qs[(gr + 8) * 40 + k + tig], qa_h[kk4][1], qa_l[kk4][1]);
        split_tf32(qs[gr * 40 + k + tig + 4], qa_h[kk4][2], qa_l[kk4][2]);
        split_tf32(qs[(gr + 8) * 40 + k + tig + 4], qa_h[kk4][3], qa_l[kk4][3]);
    }

    for (int j0 = 0; j0 < N_TOK; j0 += 64) {
#pragma unroll
        for (int it = 0; it < 2; it++) {
            int e = tid + it * 256;
            int r = e >> 3, c4 = (e & 7) * 4;
            float4 k4 = *reinterpret_cast<const float4*>(
                &g_k[(j0 + r) * D_MODEL + h * DH + c4]);
            *reinterpret_cast<float4*>(&ks[r * 40 + c4]) = k4;
        }
        __syncthreads();

        float acc[4] = {};
        int nr = wid * 8 + gr;
#pragma unroll
        for (int kk4 = 0; kk4 < 4; kk4++) {
            int k = kk4 * 8;
            unsigned bh0, bl0, bh1, bl1;
            split_tf32(ks[nr * 40 + k + tig], bh0, bl0);
            split_tf32(ks[nr * 40 + k + tig + 4], bh1, bl1);
            mma3(acc, qa_h[kk4], qa_l[kk4], bh0, bh1, bl0, bl1);
        }
        int jc = j0 + wid * 8 + 2 * tig;
        float2 b0 = *reinterpret_cast<const float2*>(
            &g_logits[((size_t)h * N_TOK + i0 + gr) * N_TOK + jc]);
        float2 b1 = *reinterpret_cast<const float2*>(
            &g_logits[((size_t)h * N_TOK + i0 + gr + 8) * N_TOK + jc]);
        Ps[gr * PSW + jc] = acc[0] + b0.x;
        Ps[gr * PSW + jc + 1] = acc[1] + b0.y;
        Ps[(gr + 8) * PSW + jc] = acc[2] + b1.x;
        Ps[(gr + 8) * PSW + jc + 1] = acc[3] + b1.y;
        __syncthreads();
    }

#pragma unroll
    for (int rr = 0; rr < 2; rr++) {
        int r = wid * 2 + rr;
        float v[24];
        float mx = -1e30f;
#pragma unroll
        for (int t = 0; t < 24; t++) {
            v[t] = Ps[r * PSW + lane + 32 * t];
            mx = fmaxf(mx, v[t]);
        }
#pragma unroll
        for (int o = 16; o; o >>= 1) mx = fmaxf(mx, __shfl_xor_sync(0xffffffffu, mx, o));
        float sum = 0.f;
#pragma unroll
        for (int t = 0; t < 24; t++) { v[t] = __expf(v[t] - mx); sum += v[t]; }
#pragma unroll
        for (int o = 16; o; o >>= 1) sum += __shfl_xor_sync(0xffffffffu, sum, o);
        float inv = 1.0f / sum;
        float* dst = &g_logits[((size_t)h * N_TOK + i0 + r) * N_TOK];
#pragma unroll
        for (int t = 0; t < 24; t++) dst[lane + 32 * t] = v[t] * inv;
    }
}

// ---------------- K3c: O = P @ V (3xTF32 MMA) ----------------
__global__ void attnv_kernel() {
    __shared__ float ps[64][68];
    __shared__ float vs[32][68];
    int h = blockIdx.y;
    int i0 = blockIdx.x * 64;
    int tid = threadIdx.x;
    int wid = tid >> 5, lane = tid & 31;
    int mtile = wid & 3, ntile = wid >> 2;
    int gr = lane >> 2, tig = lane & 3;
    float acc[2][4] = {};

    for (int j0 = 0; j0 < N_TOK; j0 += 64) {
#pragma unroll
        for (int it = 0; it < 4; it++) {
            int e = tid + it * 256;
            int r = e >> 4, c4 = (e & 15) * 4;
            float4 v = *reinterpret_cast<const float4*>(
                &g_logits[((size_t)h * N_TOK + i0 + r) * N_TOK + j0 + c4]);
            *reinterpret_cast<float4*>(&ps[r][c4]) = v;
        }
#pragma unroll
        for (int it = 0; it < 8; it++) {
            int e = tid + it * 256;
            int r = e >> 5, d = e & 31;
            vs[d][r] = g_v[(j0 + r) * D_MODEL + h * DH + d];
        }
        __syncthreads();
#pragma unroll
        for (int kk = 0; kk < 64; kk += 8) {
            int mr = mtile * 16 + gr;
            unsigned ah[4], al[4];
            split_tf32(ps[mr][kk + tig], ah[0], al[0]);
            split_tf32(ps[mr + 8][kk + tig], ah[1], al[1]);
            split_tf32(ps[mr][kk + tig + 4], ah[2], al[2]);
            split_tf32(ps[mr + 8][kk + tig + 4], ah[3], al[3]);
#pragma unroll
            for (int ni = 0; ni < 2; ni++) {
                int nr = ntile * 16 + ni * 8 + gr;
                unsigned bh0, bl0, bh1, bl1;
                split_tf32(vs[nr][kk + tig], bh0, bl0);
                split_tf32(vs[nr][kk + tig + 4], bh1, bl1);
                mma3(acc[ni], ah, al, bh0, bh1, bl0, bl1);
            }
        }
        __syncthreads();
    }
#pragma unroll
    for (int ni = 0; ni < 2; ni++) {
        int m = i0 + mtile * 16 + gr;
        int d = ntile * 16 + ni * 8 + 2 * tig;
        *reinterpret_cast<float2*>(&g_o[m * D_MODEL + h * DH + d]) =
            make_float2(acc[ni][0], acc[ni][1]);
        *reinterpret_cast<float2*>(&g_o[(m + 8) * D_MODEL + h * DH + d]) =
            make_float2(acc[ni][2], acc[ni][3]);
    }
}

// ---------------- K4: out = (o * sigmoid(g)) @ Wo^T (3xTF32 MMA) ----------------
__global__ void out_kernel(const float* __restrict__ Wo, float* __restrict__ out) {
    __shared__ float ss[128][20];
    __shared__ float ws[64][20];
    int bm = blockIdx.y * 128, bn = blockIdx.x * 64;
    int tid = threadIdx.x;
    int wid = tid >> 5, lane = tid & 31;
    int mtile = wid & 3, ntile = wid >> 2;
    int gr = lane >> 2, tig = lane & 3;
    float acc[2][4][4] = {};

    for (int k0 = 0; k0 < D_MODEL; k0 += 16) {
#pragma unroll
        for (int it = 0; it < 2; it++) {
            int e = tid + it * 256;
            int r = e >> 2, c4 = (e & 3) * 4;
            float4 va = *reinterpret_cast<const float4*>(&g_o[(bm + r) * D_MODEL + k0 + c4]);
            float4 vg = *reinterpret_cast<const float4*>(&g_g[(bm + r) * D_MODEL + k0 + c4]);
            va.x *= 1.0f / (1.0f + __expf(-vg.x));
            va.y *= 1.0f / (1.0f + __expf(-vg.y));
            va.z *= 1.0f / (1.0f + __expf(-vg.z));
            va.w *= 1.0f / (1.0f + __expf(-vg.w));
            *reinterpret_cast<float4*>(&ss[r][c4]) = va;
        }
        {
            int r = tid >> 2, c4 = (tid & 3) * 4;
            float4 v = *reinterpret_cast<const float4*>(&Wo[(bn + r) * D_MODEL + k0 + c4]);
            *reinterpret_cast<float4*>(&ws[r][c4]) = v;
        }
        __syncthreads();
#pragma unroll
        for (int kk = 0; kk < 16; kk += 8) {
            unsigned ah[2][4], al[2][4];
#pragma unroll
            for (int mi = 0; mi < 2; mi++) {
                int mr = mtile * 32 + mi * 16 + gr;
                split_tf32(ss[mr][kk + tig], ah[mi][0], al[mi][0]);
                split_tf32(ss[mr + 8][kk + tig], ah[mi][1], al[mi][1]);
                split_tf32(ss[mr][kk + tig + 4], ah[mi][2], al[mi][2]);
                split_tf32(ss[mr + 8][kk + tig + 4], ah[mi][3], al[mi][3]);
            }
#pragma unroll
            for (int ni = 0; ni < 4; ni++) {
                int nr = ntile * 32 + ni * 8 + gr;
                unsigned bh0, bl0, bh1, bl1;
                split_tf32(ws[nr][kk + tig], bh0, bl0);
                split_tf32(ws[nr][kk + tig + 4], bh1, bl1);
#pragma unroll
                for (int mi = 0; mi < 2; mi++)
                    mma3(acc[mi][ni], ah[mi], al[mi], bh0, bh1, bl0, bl1);
            }
        }
        __syncthreads();
    }
#pragma unroll
    for (int mi = 0; mi < 2; mi++) {
#pragma unroll
        for (int ni = 0; ni < 4; ni++) {
            int m = bm + mtile * 32 + mi * 16 + gr;
            int n = bn + ntile * 32 + ni * 8 + 2 * tig;
            *reinterpret_cast<float2*>(&out[m * D_MODEL + n]) =
                make_float2(acc[mi][ni][0], acc[mi][ni][1]);
            *reinterpret_cast<float2*>(&out[(m + 8) * D_MODEL + n]) =
                make_float2(acc[mi][ni][2], acc[mi][ni][3]);
        }
    }
}

// ---------------- launch ----------------
extern "C" void kernel_launch(void* const* d_in, const int* in_sizes, int n_in,
                              void* d_out, int out_size) {
    const float* s   = (const float*)d_in[0];
    const float* z   = (const float*)d_in[1];
    const float* Wq  = (const float*)d_in[2];
    const float* bq  = (const float*)d_in[3];
    const float* Wk  = (const float*)d_in[4];
    const float* Wv  = (const float*)d_in[5];
    const float* Wg  = (const float*)d_in[6];
    const float* Wo  = (const float*)d_in[7];
    const float* lnw = (const float*)d_in[8];
    const float* lnb = (const float*)d_in[9];
    const float* Wz  = (const float*)d_in[10];
    float* out = (float*)d_out;

    const int attn_smem = (16 * 40 + 64 * 40 + 16 * PSW) * 4;
    cudaFuncSetAttribute(attn_kernel, cudaFuncAttributeMaxDynamicSharedMemorySize, attn_smem);
    const int bias_smem = (2 * 64 * 132 + 16 * 132 + 128) * 4;
    cudaFuncSetAttribute(bias_kernel, cudaFuncAttributeMaxDynamicSharedMemorySize, bias_smem);

    prep_kernel<<<1, 128>>>(Wz, lnw, lnb);
    proj_kernel<<<dim3(D_MODEL / 64, N_TOK / 128, 4), 256>>>(s, Wq, bq, Wk, Wv, Wg);
    bias_kernel<<<dim3(N_TOK / 64, N_TOK / BIAS_ITILES), 256, bias_smem>>>(z);
    attn_kernel<<<dim3(N_TOK / 16, NH), 256, attn_smem>>>();
    attnv_kernel<<<dim3(N_TOK / 64, NH), 256>>>();
    out_kernel<<<dim3(D_MODEL / 64, N_TOK / 128), 256>>>(Wo, out);
}

// round 8
// speedup vs baseline: 1.0741x; 1.0488x over previous
#include <cuda_runtime.h>
#include <math.h>

#define N_TOK 768
#define D_MODEL 512
#define CZ 128
#define NH 16
#define DH 32
#define LN_EPS 1e-5f
#define PSW 776
#define BIAS_ITILES 8

// ---------------- scratch ----------------
__device__ float g_q[N_TOK * D_MODEL];
__device__ float g_k[N_TOK * D_MODEL];
__device__ float g_v[N_TOK * D_MODEL];
__device__ float g_g[N_TOK * D_MODEL];
__device__ float g_o[N_TOK * D_MODEL];
__device__ float g_logits[(size_t)NH * N_TOK * N_TOK];
__device__ float g_A[NH * CZ];
__device__ float g_SA[NH];
__device__ float g_CB[NH];

__device__ __forceinline__ unsigned f2tf32(float x) {
    unsigned r;
    asm("cvt.rna.tf32.f32 %0, %1;" : "=r"(r) : "f"(x));
    return r;
}
__device__ __forceinline__ unsigned bits(float x) { return __float_as_uint(x); }

__device__ __forceinline__ void split2(float x, float& hi, float& lo) {
    hi = __uint_as_float(f2tf32(x));
    lo = x - hi;
}

__device__ __forceinline__ void mma_tf32(float* d,
                                         unsigned a0, unsigned a1, unsigned a2, unsigned a3,
                                         unsigned b0, unsigned b1) {
    asm volatile(
        "mma.sync.aligned.m16n8k8.row.col.f32.tf32.tf32.f32 "
        "{%0,%1,%2,%3}, {%4,%5,%6,%7}, {%8,%9}, {%0,%1,%2,%3};"
        : "+f"(d[0]), "+f"(d[1]), "+f"(d[2]), "+f"(d[3])
        : "r"(a0), "r"(a1), "r"(a2), "r"(a3), "r"(b0), "r"(b1));
}

__device__ __forceinline__ void mma3(float* d, const unsigned* ah, const unsigned* al,
                                     unsigned bh0, unsigned bh1, unsigned bl0, unsigned bl1) {
    mma_tf32(d, ah[0], ah[1], ah[2], ah[3], bh0, bh1);
    mma_tf32(d, ah[0], ah[1], ah[2], ah[3], bl0, bl1);
    mma_tf32(d, al[0], al[1], al[2], al[3], bh0, bh1);
}

__device__ __forceinline__ void cp_async16(unsigned dst, const void* src) {
    asm volatile("cp.async.cg.shared.global [%0], [%1], 16;" :: "r"(dst), "l"(src));
}

// ---------------- K0: fold LN affine into Wz ----------------
__global__ void prep_kernel(const float* __restrict__ Wz,
                            const float* __restrict__ lnw,
                            const float* __restrict__ lnb) {
    __shared__ float red[8];
    int c = threadIdx.x;
    float wc = lnw[c], bc = lnb[c];
    for (int h = 0; h < NH; h++) {
        float wz = Wz[h * CZ + c];
        float a = wz * wc;
        g_A[h * CZ + c] = a;
        float sa = a, cb = wz * bc;
        for (int o = 16; o; o >>= 1) {
            sa += __shfl_down_sync(0xffffffffu, sa, o);
            cb += __shfl_down_sync(0xffffffffu, cb, o);
        }
        if ((c & 31) == 0) { red[c >> 5] = sa; red[4 + (c >> 5)] = cb; }
        __syncthreads();
        if (c == 0) {
            g_SA[h] = red[0] + red[1] + red[2] + red[3];
            g_CB[h] = red[4] + red[5] + red[6] + red[7];
        }
        __syncthreads();
    }
}

// ---------------- K1: projections, dual-plane 3xTF32, BM=BN=64 ----------------
__global__ void proj_kernel(const float* __restrict__ s,
                            const float* __restrict__ Wq, const float* __restrict__ bq,
                            const float* __restrict__ Wk, const float* __restrict__ Wv,
                            const float* __restrict__ Wg) {
    __shared__ float sh[64][20], sl[64][20], wh[64][20], wl[64][20];
    int w = blockIdx.z;
    const float* W = (w == 0) ? Wq : (w == 1) ? Wk : (w == 2) ? Wv : Wg;
    float* C = (w == 0) ? g_q : (w == 1) ? g_k : (w == 2) ? g_v : g_g;
    int bm = blockIdx.y * 64, bn = blockIdx.x * 64;
    int tid = threadIdx.x;
    int wid = tid >> 5, lane = tid & 31;
    int mtile = wid & 3, ntile = wid >> 2;
    int gr = lane >> 2, tig = lane & 3;
    int lr = tid >> 2, lc = (tid & 3) * 4;
    float acc[4][4] = {};

    for (int k0 = 0; k0 < D_MODEL; k0 += 16) {
        {
            float4 v = *reinterpret_cast<const float4*>(&s[(bm + lr) * D_MODEL + k0 + lc]);
            split2(v.x, sh[lr][lc], sl[lr][lc]);
            split2(v.y, sh[lr][lc + 1], sl[lr][lc + 1]);
            split2(v.z, sh[lr][lc + 2], sl[lr][lc + 2]);
            split2(v.w, sh[lr][lc + 3], sl[lr][lc + 3]);
            float4 u = *reinterpret_cast<const float4*>(&W[(bn + lr) * D_MODEL + k0 + lc]);
            split2(u.x, wh[lr][lc], wl[lr][lc]);
            split2(u.y, wh[lr][lc + 1], wl[lr][lc + 1]);
            split2(u.z, wh[lr][lc + 2], wl[lr][lc + 2]);
            split2(u.w, wh[lr][lc + 3], wl[lr][lc + 3]);
        }
        __syncthreads();
#pragma unroll
        for (int kk = 0; kk < 16; kk += 8) {
            int mr = mtile * 16 + gr;
            unsigned ah[4], al[4];
            ah[0] = bits(sh[mr][kk + tig]);     al[0] = bits(sl[mr][kk + tig]);
            ah[1] = bits(sh[mr + 8][kk + tig]); al[1] = bits(sl[mr + 8][kk + tig]);
            ah[2] = bits(sh[mr][kk + tig + 4]);     al[2] = bits(sl[mr][kk + tig + 4]);
            ah[3] = bits(sh[mr + 8][kk + tig + 4]); al[3] = bits(sl[mr + 8][kk + tig + 4]);
#pragma unroll
            for (int ni = 0; ni < 4; ni++) {
                int nr = ntile * 32 + ni * 8 + gr;
                unsigned bh0 = bits(wh[nr][kk + tig]), bl0 = bits(wl[nr][kk + tig]);
                unsigned bh1 = bits(wh[nr][kk + tig + 4]), bl1 = bits(wl[nr][kk + tig + 4]);
                mma3(acc[ni], ah, al, bh0, bh1, bl0, bl1);
            }
        }
        __syncthreads();
    }
#pragma unroll
    for (int ni = 0; ni < 4; ni++) {
        int m = bm + mtile * 16 + gr;
        int n = bn + ntile * 32 + ni * 8 + 2 * tig;
        float b0 = 0.f, b1 = 0.f;
        if (w == 0) { b0 = bq[n]; b1 = bq[n + 1]; }
        *reinterpret_cast<float2*>(&C[m * D_MODEL + n]) =
            make_float2(acc[ni][0] + b0, acc[ni][1] + b1);
        *reinterpret_cast<float2*>(&C[(m + 8) * D_MODEL + n]) =
            make_float2(acc[ni][2] + b0, acc[ni][3] + b1);
    }
}

// ---------------- K2: pair bias, double-buffered cp.async (r7, proven) ----------------
__global__ void bias_kernel(const float* __restrict__ z) {
    extern __shared__ float bsm[];
    float* zbuf[2] = {bsm, bsm + 64 * 132};
    float* As = bsm + 2 * 64 * 132;
    float* mu_s = As + 16 * 132;
    float* rs_s = mu_s + 64;
    int j0 = blockIdx.x * 64;
    int ibase = blockIdx.y * BIAS_ITILES;
    int tid = threadIdx.x;

    for (int e = tid; e < 16 * 32; e += 256) {
        int h = e >> 5, c4 = (e & 31) * 4;
        float4 v = *reinterpret_cast<const float4*>(&g_A[h * CZ + c4]);
        *reinterpret_cast<float4*>(&As[h * 132 + c4]) = v;
    }
    {
        const float* zb = z + ((size_t)ibase * N_TOK + j0) * CZ;
        unsigned dst = (unsigned)__cvta_generic_to_shared(zbuf[0]);
#pragma unroll
        for (int it = 0; it < 8; it++) {
            int f4 = tid + it * 256;
            int r = f4 >> 5, c4 = f4 & 31;
            cp_async16(dst + (r * 132 + c4 * 4) * 4, zb + r * CZ + c4 * 4);
        }
        asm volatile("cp.async.commit_group;");
    }

    int w = tid >> 5, lane = tid & 31;
    int mtile = w & 3, ntile = w >> 2;
    int gr = lane >> 2, tig = lane & 3;

    for (int t = 0; t < BIAS_ITILES; t++) {
        float* cur = zbuf[t & 1];
        if (t + 1 < BIAS_ITILES) {
            const float* zb = z + ((size_t)(ibase + t + 1) * N_TOK + j0) * CZ;
            unsigned dst = (unsigned)__cvta_generic_to_shared(zbuf[(t + 1) & 1]);
#pragma unroll
            for (int it = 0; it < 8; it++) {
                int f4 = tid + it * 256;
                int r = f4 >> 5, c4 = f4 & 31;
                cp_async16(dst + (r * 132 + c4 * 4) * 4, zb + r * CZ + c4 * 4);
            }
            asm volatile("cp.async.commit_group;");
            asm volatile("cp.async.wait_group 1;");
        } else {
            asm volatile("cp.async.wait_group 0;");
        }
        __syncthreads();

        {
            int row = tid >> 2, sub = tid & 3;
            float sm = 0.f, sq = 0.f;
#pragma unroll
            for (int c4 = 0; c4 < 8; c4++) {
                float4 v = *reinterpret_cast<float4*>(&cur[row * 132 + (sub * 8 + c4) * 4]);
                sm += v.x + v.y + v.z + v.w;
                sq += v.x * v.x + v.y * v.y + v.z * v.z + v.w * v.w;
            }
            sm += __shfl_xor_sync(0xffffffffu, sm, 1);
            sm += __shfl_xor_sync(0xffffffffu, sm, 2);
            sq += __shfl_xor_sync(0xffffffffu, sq, 1);
            sq += __shfl_xor_sync(0xffffffffu, sq, 2);
            if (sub == 0) {
                float m = sm * (1.0f / CZ);
                float var = sq * (1.0f / CZ) - m * m;
                mu_s[row] = m;
                rs_s[row] = rsqrtf(var + LN_EPS);
            }
        }
        __syncthreads();

        const float* zr0 = &cur[(mtile * 16 + gr) * 132];
        const float* zr1 = &cur[(mtile * 16 + gr + 8) * 132];
        const float* ar = &As[(ntile * 8 + gr) * 132];

        float d[4] = {};
#pragma unroll
        for (int k0 = 0; k0 < CZ; k0 += 8) {
            unsigned a0 = f2tf32(zr0[k0 + tig]);
            unsigned a1 = f2tf32(zr1[k0 + tig]);
            unsigned a2 = f2tf32(zr0[k0 + tig + 4]);
            unsigned a3 = f2tf32(zr1[k0 + tig + 4]);
            unsigned b0 = f2tf32(ar[k0 + tig]);
            unsigned b1 = f2tf32(ar[k0 + tig + 4]);
            mma_tf32(d, a0, a1, a2, a3, b0, b1);
        }

        int i = ibase + t;
        int jl = mtile * 16 + gr;
        int jh = jl + 8;
        int h0 = ntile * 8 + 2 * tig, h1 = h0 + 1;
        float mu_l = mu_s[jl], rs_l = rs_s[jl];
        float mu_h = mu_s[jh], rs_h = rs_s[jh];
        float sa0 = g_SA[h0], cb0 = g_CB[h0];
        float sa1 = g_SA[h1], cb1 = g_CB[h1];
        g_logits[((size_t)h0 * N_TOK + i) * N_TOK + j0 + jl] = rs_l * (d[0] - mu_l * sa0) + cb0;
        g_logits[((size_t)h1 * N_TOK + i) * N_TOK + j0 + jl] = rs_l * (d[1] - mu_l * sa1) + cb1;
        g_logits[((size_t)h0 * N_TOK + i) * N_TOK + j0 + jh] = rs_h * (d[2] - mu_h * sa0) + cb0;
        g_logits[((size_t)h1 * N_TOK + i) * N_TOK + j0 + jh] = rs_h * (d[3] - mu_h * sa1) + cb1;
        __syncthreads();
    }
}

// ---------------- K3: fused logits + bias + softmax, dual-plane K ----------------
__global__ void attn_kernel() {
    extern __shared__ float sm_[];
    float* qs = sm_;                        // [16][36]
    float* ksh = qs + 16 * 36;              // [64][36]
    float* ksl = ksh + 64 * 36;             // [64][36]
    float* Ps = ksl + 64 * 36;              // [16][PSW]
    int h = blockIdx.y;
    int i0 = blockIdx.x * 16;
    int tid = threadIdx.x;
    int wid = tid >> 5, lane = tid & 31;
    int gr = lane >> 2, tig = lane & 3;
    const float scale = 0.17677669529663687f;

    if (tid < 128) {
        int r = tid >> 3, c4 = (tid & 7) * 4;
        float4 q = *reinterpret_cast<const float4*>(&g_q[(i0 + r) * D_MODEL + h * DH + c4]);
        q.x *= scale; q.y *= scale; q.z *= scale; q.w *= scale;
        *reinterpret_cast<float4*>(&qs[r * 36 + c4]) = q;
    }
    __syncthreads();

    unsigned qa_h[4][4], qa_l[4][4];
#pragma unroll
    for (int kk4 = 0; kk4 < 4; kk4++) {
        int k = kk4 * 8;
        float hi, lo;
        split2(qs[gr * 36 + k + tig], hi, lo);       qa_h[kk4][0] = bits(hi); qa_l[kk4][0] = bits(lo);
        split2(qs[(gr + 8) * 36 + k + tig], hi, lo); qa_h[kk4][1] = bits(hi); qa_l[kk4][1] = bits(lo);
        split2(qs[gr * 36 + k + tig + 4], hi, lo);       qa_h[kk4][2] = bits(hi); qa_l[kk4][2] = bits(lo);
        split2(qs[(gr + 8) * 36 + k + tig + 4], hi, lo); qa_h[kk4][3] = bits(hi); qa_l[kk4][3] = bits(lo);
    }

    for (int j0 = 0; j0 < N_TOK; j0 += 64) {
#pragma unroll
        for (int it = 0; it < 2; it++) {
            int e = tid + it * 256;
            int r = e >> 3, c4 = (e & 7) * 4;
            float4 k4 = *reinterpret_cast<const float4*>(
                &g_k[(j0 + r) * D_MODEL + h * DH + c4]);
            split2(k4.x, ksh[r * 36 + c4], ksl[r * 36 + c4]);
            split2(k4.y, ksh[r * 36 + c4 + 1], ksl[r * 36 + c4 + 1]);
            split2(k4.z, ksh[r * 36 + c4 + 2], ksl[r * 36 + c4 + 2]);
            split2(k4.w, ksh[r * 36 + c4 + 3], ksl[r * 36 + c4 + 3]);
        }
        __syncthreads();

        float acc[4] = {};
        int nr = wid * 8 + gr;
#pragma unroll
        for (int kk4 = 0; kk4 < 4; kk4++) {
            int k = kk4 * 8;
            unsigned bh0 = bits(ksh[nr * 36 + k + tig]), bl0 = bits(ksl[nr * 36 + k + tig]);
            unsigned bh1 = bits(ksh[nr * 36 + k + tig + 4]), bl1 = bits(ksl[nr * 36 + k + tig + 4]);
            mma3(acc, qa_h[kk4], qa_l[kk4], bh0, bh1, bl0, bl1);
        }
        int jc = j0 + wid * 8 + 2 * tig;
        float2 b0 = *reinterpret_cast<const float2*>(
            &g_logits[((size_t)h * N_TOK + i0 + gr) * N_TOK + jc]);
        float2 b1 = *reinterpret_cast<const float2*>(
            &g_logits[((size_t)h * N_TOK + i0 + gr + 8) * N_TOK + jc]);
        Ps[gr * PSW + jc] = acc[0] + b0.x;
        Ps[gr * PSW + jc + 1] = acc[1] + b0.y;
        Ps[(gr + 8) * PSW + jc] = acc[2] + b1.x;
        Ps[(gr + 8) * PSW + jc + 1] = acc[3] + b1.y;
        __syncthreads();
    }

#pragma unroll
    for (int rr = 0; rr < 2; rr++) {
        int r = wid * 2 + rr;
        float v[24];
        float mx = -1e30f;
#pragma unroll
        for (int t = 0; t < 24; t++) {
            v[t] = Ps[r * PSW + lane + 32 * t];
            mx = fmaxf(mx, v[t]);
        }
#pragma unroll
        for (int o = 16; o; o >>= 1) mx = fmaxf(mx, __shfl_xor_sync(0xffffffffu, mx, o));
        float sum = 0.f;
#pragma unroll
        for (int t = 0; t < 24; t++) { v[t] = __expf(v[t] - mx); sum += v[t]; }
#pragma unroll
        for (int o = 16; o; o >>= 1) sum += __shfl_xor_sync(0xffffffffu, sum, o);
        float inv = 1.0f / sum;
        float* dst = &g_logits[((size_t)h * N_TOK + i0 + r) * N_TOK];
#pragma unroll
        for (int t = 0; t < 24; t++) dst[lane + 32 * t] = v[t] * inv;
    }
}

// ---------------- K3c: O = P @ V, dual-plane, 32-row tiles ----------------
__global__ void attnv_kernel() {
    __shared__ float psh[32][68], psl[32][68];
    __shared__ float vsh[32][68], vsl[32][68];
    int h = blockIdx.y;
    int i0 = blockIdx.x * 32;
    int tid = threadIdx.x;
    int wid = tid >> 5, lane = tid & 31;
    int mtile = wid & 1, ntile = wid >> 1;
    int gr = lane >> 2, tig = lane & 3;
    float acc[4] = {};

    for (int j0 = 0; j0 < N_TOK; j0 += 64) {
#pragma unroll
        for (int it = 0; it < 2; it++) {
            int e = tid + it * 256;
            int r = e >> 4, c4 = (e & 15) * 4;
            float4 v = *reinterpret_cast<const float4*>(
                &g_logits[((size_t)h * N_TOK + i0 + r) * N_TOK + j0 + c4]);
            split2(v.x, psh[r][c4], psl[r][c4]);
            split2(v.y, psh[r][c4 + 1], psl[r][c4 + 1]);
            split2(v.z, psh[r][c4 + 2], psl[r][c4 + 2]);
            split2(v.w, psh[r][c4 + 3], psl[r][c4 + 3]);
        }
#pragma unroll
        for (int it = 0; it < 8; it++) {
            int e = tid + it * 256;
            int r = e >> 5, d = e & 31;
            float v = g_v[(j0 + r) * D_MODEL + h * DH + d];
            split2(v, vsh[d][r], vsl[d][r]);
        }
        __syncthreads();
#pragma unroll
        for (int kk = 0; kk < 64; kk += 8) {
            int mr = mtile * 16 + gr;
            unsigned ah[4], al[4];
            ah[0] = bits(psh[mr][kk + tig]);     al[0] = bits(psl[mr][kk + tig]);
            ah[1] = bits(psh[mr + 8][kk + tig]); al[1] = bits(psl[mr + 8][kk + tig]);
            ah[2] = bits(psh[mr][kk + tig + 4]);     al[2] = bits(psl[mr][kk + tig + 4]);
            ah[3] = bits(psh[mr + 8][kk + tig + 4]); al[3] = bits(psl[mr + 8][kk + tig + 4]);
            int nr = ntile * 8 + gr;
            unsigned bh0 = bits(vsh[nr][kk + tig]), bl0 = bits(vsl[nr][kk + tig]);
            unsigned bh1 = bits(vsh[nr][kk + tig + 4]), bl1 = bits(vsl[nr][kk + tig + 4]);
            mma3(acc, ah, al, bh0, bh1, bl0, bl1);
        }
        __syncthreads();
    }
    int m = i0 + mtile * 16 + gr;
    int d = ntile * 8 + 2 * tig;
    *reinterpret_cast<float2*>(&g_o[m * D_MODEL + h * DH + d]) = make_float2(acc[0], acc[1]);
    *reinterpret_cast<float2*>(&g_o[(m + 8) * D_MODEL + h * DH + d]) = make_float2(acc[2], acc[3]);
}

// ---------------- K4: out = (o * sigmoid(g)) @ Wo^T, dual-plane, BM=BN=64 ----------------
__global__ void out_kernel(const float* __restrict__ Wo, float* __restrict__ out) {
    __shared__ float sh[64][20], sl[64][20], wh[64][20], wl[64][20];
    int bm = blockIdx.y * 64, bn = blockIdx.x * 64;
    int tid = threadIdx.x;
    int wid = tid >> 5, lane = tid & 31;
    int mtile = wid & 3, ntile = wid >> 2;
    int gr = lane >> 2, tig = lane & 3;
    int lr = tid >> 2, lc = (tid & 3) * 4;
    float acc[4][4] = {};

    for (int k0 = 0; k0 < D_MODEL; k0 += 16) {
        {
            float4 va = *reinterpret_cast<const float4*>(&g_o[(bm + lr) * D_MODEL + k0 + lc]);
            float4 vg = *reinterpret_cast<const float4*>(&g_g[(bm + lr) * D_MODEL + k0 + lc]);
            va.x *= 1.0f / (1.0f + __expf(-vg.x));
            va.y *= 1.0f / (1.0f + __expf(-vg.y));
            va.z *= 1.0f / (1.0f + __expf(-vg.z));
            va.w *= 1.0f / (1.0f + __expf(-vg.w));
            split2(va.x, sh[lr][lc], sl[lr][lc]);
            split2(va.y, sh[lr][lc + 1], sl[lr][lc + 1]);
            split2(va.z, sh[lr][lc + 2], sl[lr][lc + 2]);
            split2(va.w, sh[lr][lc + 3], sl[lr][lc + 3]);
            float4 u = *reinterpret_cast<const float4*>(&Wo[(bn + lr) * D_MODEL + k0 + lc]);
            split2(u.x, wh[lr][lc], wl[lr][lc]);
            split2(u.y, wh[lr][lc + 1], wl[lr][lc + 1]);
            split2(u.z, wh[lr][lc + 2], wl[lr][lc + 2]);
            split2(u.w, wh[lr][lc + 3], wl[lr][lc + 3]);
        }
        __syncthreads();
#pragma unroll
        for (int kk = 0; kk < 16; kk += 8) {
            int mr = mtile * 16 + gr;
            unsigned ah[4], al[4];
            ah[0] = bits(sh[mr][kk + tig]);     al[0] = bits(sl[mr][kk + tig]);
            ah[1] = bits(sh[mr + 8][kk + tig]); al[1] = bits(sl[mr + 8][kk + tig]);
            ah[2] = bits(sh[mr][kk + tig + 4]);     al[2] = bits(sl[mr][kk + tig + 4]);
            ah[3] = bits(sh[mr + 8][kk + tig + 4]); al[3] = bits(sl[mr + 8][kk + tig + 4]);
#pragma unroll
            for (int ni = 0; ni < 4; ni++) {
                int nr = ntile * 32 + ni * 8 + gr;
                unsigned bh0 = bits(wh[nr][kk + tig]), bl0 = bits(wl[nr][kk + tig]);
                unsigned bh1 = bits(wh[nr][kk + tig + 4]), bl1 = bits(wl[nr][kk + tig + 4]);
                mma3(acc[ni], ah, al, bh0, bh1, bl0, bl1);
            }
        }
        __syncthreads();
    }
#pragma unroll
    for (int ni = 0; ni < 4; ni++) {
        int m = bm + mtile * 16 + gr;
        int n = bn + ntile * 32 + ni * 8 + 2 * tig;
        *reinterpret_cast<float2*>(&out[m * D_MODEL + n]) = make_float2(acc[ni][0], acc[ni][1]);
        *reinterpret_cast<float2*>(&out[(m + 8) * D_MODEL + n]) = make_float2(acc[ni][2], acc[ni][3]);
    }
}

// ---------------- launch ----------------
extern "C" void kernel_launch(void* const* d_in, const int* in_sizes, int n_in,
                              void* d_out, int out_size) {
    const float* s   = (const float*)d_in[0];
    const float* z   = (const float*)d_in[1];
    const float* Wq  = (const float*)d_in[2];
    const float* bq  = (const float*)d_in[3];
    const float* Wk  = (const float*)d_in[4];
    const float* Wv  = (const float*)d_in[5];
    const float* Wg  = (const float*)d_in[6];
    const float* Wo  = (const float*)d_in[7];
    const float* lnw = (const float*)d_in[8];
    const float* lnb = (const float*)d_in[9];
    const float* Wz  = (const float*)d_in[10];
    float* out = (float*)d_out;

    const int attn_smem = (16 * 36 + 2 * 64 * 36 + 16 * PSW) * 4;
    cudaFuncSetAttribute(attn_kernel, cudaFuncAttributeMaxDynamicSharedMemorySize, attn_smem);
    const int bias_smem = (2 * 64 * 132 + 16 * 132 + 128) * 4;
    cudaFuncSetAttribute(bias_kernel, cudaFuncAttributeMaxDynamicSharedMemorySize, bias_smem);

    prep_kernel<<<1, 128>>>(Wz, lnw, lnb);
    proj_kernel<<<dim3(D_MODEL / 64, N_TOK / 64, 4), 256>>>(s, Wq, bq, Wk, Wv, Wg);
    bias_kernel<<<dim3(N_TOK / 64, N_TOK / BIAS_ITILES), 256, bias_smem>>>(z);
    attn_kernel<<<dim3(N_TOK / 16, NH), 256, attn_smem>>>();
    attnv_kernel<<<dim3(N_TOK / 32, NH), 256>>>();
    out_kernel<<<dim3(D_MODEL / 64, N_TOK / 64), 256>>>(Wo, out);
}

// round 9
// speedup vs baseline: 1.0800x; 1.0055x over previous
#include <cuda_runtime.h>
#include <math.h>

#define N_TOK 768
#define D_MODEL 512
#define CZ 128
#define NH 16
#define DH 32
#define LN_EPS 1e-5f
#define PSW 776
#define BIAS_ITILES 8

// ---------------- scratch ----------------
__device__ float g_q[N_TOK * D_MODEL];
__device__ float g_k[N_TOK * D_MODEL];
__device__ float g_v[N_TOK * D_MODEL];
__device__ float g_g[N_TOK * D_MODEL];
__device__ float g_o[N_TOK * D_MODEL];
__device__ float g_logits[(size_t)NH * N_TOK * N_TOK];  // bias only (read by attn)
__device__ float g_A[NH * CZ];
__device__ float g_SA[NH];
__device__ float g_CB[NH];

__device__ __forceinline__ unsigned f2tf32(float x) {
    unsigned r;
    asm("cvt.rna.tf32.f32 %0, %1;" : "=r"(r) : "f"(x));
    return r;
}
__device__ __forceinline__ unsigned bits(float x) { return __float_as_uint(x); }

__device__ __forceinline__ void split2(float x, float& hi, float& lo) {
    hi = __uint_as_float(f2tf32(x));
    lo = x - hi;
}

__device__ __forceinline__ void mma_tf32(float* d,
                                         unsigned a0, unsigned a1, unsigned a2, unsigned a3,
                                         unsigned b0, unsigned b1) {
    asm volatile(
        "mma.sync.aligned.m16n8k8.row.col.f32.tf32.tf32.f32 "
        "{%0,%1,%2,%3}, {%4,%5,%6,%7}, {%8,%9}, {%0,%1,%2,%3};"
        : "+f"(d[0]), "+f"(d[1]), "+f"(d[2]), "+f"(d[3])
        : "r"(a0), "r"(a1), "r"(a2), "r"(a3), "r"(b0), "r"(b1));
}

__device__ __forceinline__ void mma3(float* d, const unsigned* ah, const unsigned* al,
                                     unsigned bh0, unsigned bh1, unsigned bl0, unsigned bl1) {
    mma_tf32(d, ah[0], ah[1], ah[2], ah[3], bh0, bh1);
    mma_tf32(d, ah[0], ah[1], ah[2], ah[3], bl0, bl1);
    mma_tf32(d, al[0], al[1], al[2], al[3], bh0, bh1);
}

__device__ __forceinline__ void cp_async16(unsigned dst, const void* src) {
    asm volatile("cp.async.cg.shared.global [%0], [%1], 16;" :: "r"(dst), "l"(src));
}

// ---------------- K0: fold LN affine into Wz ----------------
__global__ void prep_kernel(const float* __restrict__ Wz,
                            const float* __restrict__ lnw,
                            const float* __restrict__ lnb) {
    __shared__ float red[8];
    int c = threadIdx.x;
    float wc = lnw[c], bc = lnb[c];
    for (int h = 0; h < NH; h++) {
        float wz = Wz[h * CZ + c];
        float a = wz * wc;
        g_A[h * CZ + c] = a;
        float sa = a, cb = wz * bc;
        for (int o = 16; o; o >>= 1) {
            sa += __shfl_down_sync(0xffffffffu, sa, o);
            cb += __shfl_down_sync(0xffffffffu, cb, o);
        }
        if ((c & 31) == 0) { red[c >> 5] = sa; red[4 + (c >> 5)] = cb; }
        __syncthreads();
        if (c == 0) {
            g_SA[h] = red[0] + red[1] + red[2] + red[3];
            g_CB[h] = red[4] + red[5] + red[6] + red[7];
        }
        __syncthreads();
    }
}

// ---------------- K1: projections, dual-plane 3xTF32, BM=BN=64 ----------------
__global__ void proj_kernel(const float* __restrict__ s,
                            const float* __restrict__ Wq, const float* __restrict__ bq,
                            const float* __restrict__ Wk, const float* __restrict__ Wv,
                            const float* __restrict__ Wg) {
    __shared__ float sh[64][20], sl[64][20], wh[64][20], wl[64][20];
    int w = blockIdx.z;
    const float* W = (w == 0) ? Wq : (w == 1) ? Wk : (w == 2) ? Wv : Wg;
    float* C = (w == 0) ? g_q : (w == 1) ? g_k : (w == 2) ? g_v : g_g;
    int bm = blockIdx.y * 64, bn = blockIdx.x * 64;
    int tid = threadIdx.x;
    int wid = tid >> 5, lane = tid & 31;
    int mtile = wid & 3, ntile = wid >> 2;
    int gr = lane >> 2, tig = lane & 3;
    int lr = tid >> 2, lc = (tid & 3) * 4;
    float acc[4][4] = {};

    for (int k0 = 0; k0 < D_MODEL; k0 += 16) {
        {
            float4 v = *reinterpret_cast<const float4*>(&s[(bm + lr) * D_MODEL + k0 + lc]);
            split2(v.x, sh[lr][lc], sl[lr][lc]);
            split2(v.y, sh[lr][lc + 1], sl[lr][lc + 1]);
            split2(v.z, sh[lr][lc + 2], sl[lr][lc + 2]);
            split2(v.w, sh[lr][lc + 3], sl[lr][lc + 3]);
            float4 u = *reinterpret_cast<const float4*>(&W[(bn + lr) * D_MODEL + k0 + lc]);
            split2(u.x, wh[lr][lc], wl[lr][lc]);
            split2(u.y, wh[lr][lc + 1], wl[lr][lc + 1]);
            split2(u.z, wh[lr][lc + 2], wl[lr][lc + 2]);
            split2(u.w, wh[lr][lc + 3], wl[lr][lc + 3]);
        }
        __syncthreads();
#pragma unroll
        for (int kk = 0; kk < 16; kk += 8) {
            int mr = mtile * 16 + gr;
            unsigned ah[4], al[4];
            ah[0] = bits(sh[mr][kk + tig]);     al[0] = bits(sl[mr][kk + tig]);
            ah[1] = bits(sh[mr + 8][kk + tig]); al[1] = bits(sl[mr + 8][kk + tig]);
            ah[2] = bits(sh[mr][kk + tig + 4]);     al[2] = bits(sl[mr][kk + tig + 4]);
            ah[3] = bits(sh[mr + 8][kk + tig + 4]); al[3] = bits(sl[mr + 8][kk + tig + 4]);
#pragma unroll
            for (int ni = 0; ni < 4; ni++) {
                int nr = ntile * 32 + ni * 8 + gr;
                unsigned bh0 = bits(wh[nr][kk + tig]), bl0 = bits(wl[nr][kk + tig]);
                unsigned bh1 = bits(wh[nr][kk + tig + 4]), bl1 = bits(wl[nr][kk + tig + 4]);
                mma3(acc[ni], ah, al, bh0, bh1, bl0, bl1);
            }
        }
        __syncthreads();
    }
#pragma unroll
    for (int ni = 0; ni < 4; ni++) {
        int m = bm + mtile * 16 + gr;
        int n = bn + ntile * 32 + ni * 8 + 2 * tig;
        float b0 = 0.f, b1 = 0.f;
        if (w == 0) { b0 = bq[n]; b1 = bq[n + 1]; }
        *reinterpret_cast<float2*>(&C[m * D_MODEL + n]) =
            make_float2(acc[ni][0] + b0, acc[ni][1] + b1);
        *reinterpret_cast<float2*>(&C[(m + 8) * D_MODEL + n]) =
            make_float2(acc[ni][2] + b0, acc[ni][3] + b1);
    }
}

// ---------------- K2: pair bias, double-buffered cp.async (proven) ----------------
__global__ void bias_kernel(const float* __restrict__ z) {
    extern __shared__ float bsm[];
    float* zbuf[2] = {bsm, bsm + 64 * 132};
    float* As = bsm + 2 * 64 * 132;
    float* mu_s = As + 16 * 132;
    float* rs_s = mu_s + 64;
    int j0 = blockIdx.x * 64;
    int ibase = blockIdx.y * BIAS_ITILES;
    int tid = threadIdx.x;

    for (int e = tid; e < 16 * 32; e += 256) {
        int h = e >> 5, c4 = (e & 31) * 4;
        float4 v = *reinterpret_cast<const float4*>(&g_A[h * CZ + c4]);
        *reinterpret_cast<float4*>(&As[h * 132 + c4]) = v;
    }
    {
        const float* zb = z + ((size_t)ibase * N_TOK + j0) * CZ;
        unsigned dst = (unsigned)__cvta_generic_to_shared(zbuf[0]);
#pragma unroll
        for (int it = 0; it < 8; it++) {
            int f4 = tid + it * 256;
            int r = f4 >> 5, c4 = f4 & 31;
            cp_async16(dst + (r * 132 + c4 * 4) * 4, zb + r * CZ + c4 * 4);
        }
        asm volatile("cp.async.commit_group;");
    }

    int w = tid >> 5, lane = tid & 31;
    int mtile = w & 3, ntile = w >> 2;
    int gr = lane >> 2, tig = lane & 3;

    for (int t = 0; t < BIAS_ITILES; t++) {
        float* cur = zbuf[t & 1];
        if (t + 1 < BIAS_ITILES) {
            const float* zb = z + ((size_t)(ibase + t + 1) * N_TOK + j0) * CZ;
            unsigned dst = (unsigned)__cvta_generic_to_shared(zbuf[(t + 1) & 1]);
#pragma unroll
            for (int it = 0; it < 8; it++) {
                int f4 = tid + it * 256;
                int r = f4 >> 5, c4 = f4 & 31;
                cp_async16(dst + (r * 132 + c4 * 4) * 4, zb + r * CZ + c4 * 4);
            }
            asm volatile("cp.async.commit_group;");
            asm volatile("cp.async.wait_group 1;");
        } else {
            asm volatile("cp.async.wait_group 0;");
        }
        __syncthreads();

        {
            int row = tid >> 2, sub = tid & 3;
            float sm = 0.f, sq = 0.f;
#pragma unroll
            for (int c4 = 0; c4 < 8; c4++) {
                float4 v = *reinterpret_cast<float4*>(&cur[row * 132 + (sub * 8 + c4) * 4]);
                sm += v.x + v.y + v.z + v.w;
                sq += v.x * v.x + v.y * v.y + v.z * v.z + v.w * v.w;
            }
            sm += __shfl_xor_sync(0xffffffffu, sm, 1);
            sm += __shfl_xor_sync(0xffffffffu, sm, 2);
            sq += __shfl_xor_sync(0xffffffffu, sq, 1);
            sq += __shfl_xor_sync(0xffffffffu, sq, 2);
            if (sub == 0) {
                float m = sm * (1.0f / CZ);
                float var = sq * (1.0f / CZ) - m * m;
                mu_s[row] = m;
                rs_s[row] = rsqrtf(var + LN_EPS);
            }
        }
        __syncthreads();

        const float* zr0 = &cur[(mtile * 16 + gr) * 132];
        const float* zr1 = &cur[(mtile * 16 + gr + 8) * 132];
        const float* ar = &As[(ntile * 8 + gr) * 132];

        float d[4] = {};
#pragma unroll
        for (int k0 = 0; k0 < CZ; k0 += 8) {
            unsigned a0 = f2tf32(zr0[k0 + tig]);
            unsigned a1 = f2tf32(zr1[k0 + tig]);
            unsigned a2 = f2tf32(zr0[k0 + tig + 4]);
            unsigned a3 = f2tf32(zr1[k0 + tig + 4]);
            unsigned b0 = f2tf32(ar[k0 + tig]);
            unsigned b1 = f2tf32(ar[k0 + tig + 4]);
            mma_tf32(d, a0, a1, a2, a3, b0, b1);
        }

        int i = ibase + t;
        int jl = mtile * 16 + gr;
        int jh = jl + 8;
        int h0 = ntile * 8 + 2 * tig, h1 = h0 + 1;
        float mu_l = mu_s[jl], rs_l = rs_s[jl];
        float mu_h = mu_s[jh], rs_h = rs_s[jh];
        float sa0 = g_SA[h0], cb0 = g_CB[h0];
        float sa1 = g_SA[h1], cb1 = g_CB[h1];
        g_logits[((size_t)h0 * N_TOK + i) * N_TOK + j0 + jl] = rs_l * (d[0] - mu_l * sa0) + cb0;
        g_logits[((size_t)h1 * N_TOK + i) * N_TOK + j0 + jl] = rs_l * (d[1] - mu_l * sa1) + cb1;
        g_logits[((size_t)h0 * N_TOK + i) * N_TOK + j0 + jh] = rs_h * (d[2] - mu_h * sa0) + cb0;
        g_logits[((size_t)h1 * N_TOK + i) * N_TOK + j0 + jh] = rs_h * (d[3] - mu_h * sa1) + cb1;
        __syncthreads();
    }
}

// ---------------- K3: fully fused attention: QK+bias -> softmax -> P@V -> g_o ----------------
// block = (16 q-rows, head), 256 thr = 8 warps.
// Phase 1: per 64-j tile, warp w owns j-cols w*8; logits parked in Ps (smem).
// Softmax: exp'd values stay in Ps; 1/sum in inv_s.
// Phase 2: warps (ni = w&3, k-half = w>>2) compute P@V over reused K smem; reduce; scale; store.
__global__ void attn_kernel() {
    extern __shared__ float sm_[];
    float* qs  = sm_;                   // [16][36]  (reused as reduction buffer in phase 2)
    float* ksh = qs + 16 * 36;          // [64][36] K hi   / phase2: V hi [32][68]
    float* ksl = ksh + 64 * 36;         // [64][36] K lo   / phase2: V lo [32][68]
    float* Ps  = ksl + 64 * 36;         // [16][PSW]
    float* inv_s = Ps + 16 * PSW;       // [16]
    int h = blockIdx.y;
    int i0 = blockIdx.x * 16;
    int tid = threadIdx.x;
    int wid = tid >> 5, lane = tid & 31;
    int gr = lane >> 2, tig = lane & 3;
    const float scale = 0.17677669529663687f;

    if (tid < 128) {
        int r = tid >> 3, c4 = (tid & 7) * 4;
        float4 q = *reinterpret_cast<const float4*>(&g_q[(i0 + r) * D_MODEL + h * DH + c4]);
        q.x *= scale; q.y *= scale; q.z *= scale; q.w *= scale;
        *reinterpret_cast<float4*>(&qs[r * 36 + c4]) = q;
    }
    __syncthreads();

    unsigned qa_h[4][4], qa_l[4][4];
#pragma unroll
    for (int kk4 = 0; kk4 < 4; kk4++) {
        int k = kk4 * 8;
        float hi, lo;
        split2(qs[gr * 36 + k + tig], hi, lo);       qa_h[kk4][0] = bits(hi); qa_l[kk4][0] = bits(lo);
        split2(qs[(gr + 8) * 36 + k + tig], hi, lo); qa_h[kk4][1] = bits(hi); qa_l[kk4][1] = bits(lo);
        split2(qs[gr * 36 + k + tig + 4], hi, lo);       qa_h[kk4][2] = bits(hi); qa_l[kk4][2] = bits(lo);
        split2(qs[(gr + 8) * 36 + k + tig + 4], hi, lo); qa_h[kk4][3] = bits(hi); qa_l[kk4][3] = bits(lo);
    }
    __syncthreads();  // qs reads done (phase-2 reduction reuses qs)

    // ---- Phase 1: logits + bias -> Ps ----
    for (int j0 = 0; j0 < N_TOK; j0 += 64) {
#pragma unroll
        for (int it = 0; it < 2; it++) {
            int e = tid + it * 256;
            int r = e >> 3, c4 = (e & 7) * 4;
            float4 k4 = *reinterpret_cast<const float4*>(
                &g_k[(j0 + r) * D_MODEL + h * DH + c4]);
            split2(k4.x, ksh[r * 36 + c4], ksl[r * 36 + c4]);
            split2(k4.y, ksh[r * 36 + c4 + 1], ksl[r * 36 + c4 + 1]);
            split2(k4.z, ksh[r * 36 + c4 + 2], ksl[r * 36 + c4 + 2]);
            split2(k4.w, ksh[r * 36 + c4 + 3], ksl[r * 36 + c4 + 3]);
        }
        __syncthreads();

        float acc[4] = {};
        int nr = wid * 8 + gr;
#pragma unroll
        for (int kk4 = 0; kk4 < 4; kk4++) {
            int k = kk4 * 8;
            unsigned bh0 = bits(ksh[nr * 36 + k + tig]), bl0 = bits(ksl[nr * 36 + k + tig]);
            unsigned bh1 = bits(ksh[nr * 36 + k + tig + 4]), bl1 = bits(ksl[nr * 36 + k + tig + 4]);
            mma3(acc, qa_h[kk4], qa_l[kk4], bh0, bh1, bl0, bl1);
        }
        int jc = j0 + wid * 8 + 2 * tig;
        float2 b0 = *reinterpret_cast<const float2*>(
            &g_logits[((size_t)h * N_TOK + i0 + gr) * N_TOK + jc]);
        float2 b1 = *reinterpret_cast<const float2*>(
            &g_logits[((size_t)h * N_TOK + i0 + gr + 8) * N_TOK + jc]);
        Ps[gr * PSW + jc] = acc[0] + b0.x;
        Ps[gr * PSW + jc + 1] = acc[1] + b0.y;
        Ps[(gr + 8) * PSW + jc] = acc[2] + b1.x;
        Ps[(gr + 8) * PSW + jc + 1] = acc[3] + b1.y;
        __syncthreads();
    }

    // ---- Softmax: keep exp'd values in Ps, 1/sum in inv_s ----
#pragma unroll
    for (int rr = 0; rr < 2; rr++) {
        int r = wid * 2 + rr;
        float v[24];
        float mx = -1e30f;
#pragma unroll
        for (int t = 0; t < 24; t++) {
            v[t] = Ps[r * PSW + lane + 32 * t];
            mx = fmaxf(mx, v[t]);
        }
#pragma unroll
        for (int o = 16; o; o >>= 1) mx = fmaxf(mx, __shfl_xor_sync(0xffffffffu, mx, o));
        float sum = 0.f;
#pragma unroll
        for (int t = 0; t < 24; t++) { v[t] = __expf(v[t] - mx); sum += v[t]; }
#pragma unroll
        for (int o = 16; o; o >>= 1) sum += __shfl_xor_sync(0xffffffffu, sum, o);
        if (lane == 0) inv_s[r] = 1.0f / sum;
#pragma unroll
        for (int t = 0; t < 24; t++) Ps[r * PSW + lane + 32 * t] = v[t];
    }
    __syncthreads();

    // ---- Phase 2: O = P @ V (split-k over warp halves), reuse K smem for V ----
    int ni = wid & 3, kh = wid >> 2;
    float acc[4] = {};
    for (int j0 = 0; j0 < N_TOK; j0 += 64) {
#pragma unroll
        for (int it = 0; it < 8; it++) {
            int e = tid + it * 256;
            int r = e >> 5, d = e & 31;
            float v = g_v[(j0 + r) * D_MODEL + h * DH + d];
            split2(v, ksh[d * 68 + r], ksl[d * 68 + r]);
        }
        __syncthreads();
#pragma unroll
        for (int kk = 0; kk < 32; kk += 8) {
            int klocal = kh * 32 + kk;
            int kg = j0 + klocal;
            unsigned ah[4], al[4];
            float hi, lo;
            split2(Ps[gr * PSW + kg + tig], hi, lo);           ah[0] = bits(hi); al[0] = bits(lo);
            split2(Ps[(gr + 8) * PSW + kg + tig], hi, lo);     ah[1] = bits(hi); al[1] = bits(lo);
            split2(Ps[gr * PSW + kg + tig + 4], hi, lo);       ah[2] = bits(hi); al[2] = bits(lo);
            split2(Ps[(gr + 8) * PSW + kg + tig + 4], hi, lo); ah[3] = bits(hi); al[3] = bits(lo);
            int nr = ni * 8 + gr;
            unsigned bh0 = bits(ksh[nr * 68 + klocal + tig]), bl0 = bits(ksl[nr * 68 + klocal + tig]);
            unsigned bh1 = bits(ksh[nr * 68 + klocal + tig + 4]), bl1 = bits(ksl[nr * 68 + klocal + tig + 4]);
            mma3(acc, ah, al, bh0, bh1, bl0, bl1);
        }
        __syncthreads();
    }

    // cross-half reduction (warps 4-7 -> qs buffer; warps 0-3 add + store)
    float* red = qs;  // 576 floats >= 512
    if (kh == 1) {
#pragma unroll
        for (int t = 0; t < 4; t++) red[ni * 128 + lane * 4 + t] = acc[t];
    }
    __syncthreads();
    if (kh == 0) {
#pragma unroll
        for (int t = 0; t < 4; t++) acc[t] += red[ni * 128 + lane * 4 + t];
        int n = ni * 8 + 2 * tig;
        float iv0 = inv_s[gr], iv1 = inv_s[gr + 8];
        *reinterpret_cast<float2*>(&g_o[(i0 + gr) * D_MODEL + h * DH + n]) =
            make_float2(acc[0] * iv0, acc[1] * iv0);
        *reinterpret_cast<float2*>(&g_o[(i0 + gr + 8) * D_MODEL + h * DH + n]) =
            make_float2(acc[2] * iv1, acc[3] * iv1);
    }
}

// ---------------- K4: out = (o * sigmoid(g)) @ Wo^T, dual-plane, BM=BN=64 ----------------
__global__ void out_kernel(const float* __restrict__ Wo, float* __restrict__ out) {
    __shared__ float sh[64][20], sl[64][20], wh[64][20], wl[64][20];
    int bm = blockIdx.y * 64, bn = blockIdx.x * 64;
    int tid = threadIdx.x;
    int wid = tid >> 5, lane = tid & 31;
    int mtile = wid & 3, ntile = wid >> 2;
    int gr = lane >> 2, tig = lane & 3;
    int lr = tid >> 2, lc = (tid & 3) * 4;
    float acc[4][4] = {};

    for (int k0 = 0; k0 < D_MODEL; k0 += 16) {
        {
            float4 va = *reinterpret_cast<const float4*>(&g_o[(bm + lr) * D_MODEL + k0 + lc]);
            float4 vg = *reinterpret_cast<const float4*>(&g_g[(bm + lr) * D_MODEL + k0 + lc]);
            va.x *= 1.0f / (1.0f + __expf(-vg.x));
            va.y *= 1.0f / (1.0f + __expf(-vg.y));
            va.z *= 1.0f / (1.0f + __expf(-vg.z));
            va.w *= 1.0f / (1.0f + __expf(-vg.w));
            split2(va.x, sh[lr][lc], sl[lr][lc]);
            split2(va.y, sh[lr][lc + 1], sl[lr][lc + 1]);
            split2(va.z, sh[lr][lc + 2], sl[lr][lc + 2]);
            split2(va.w, sh[lr][lc + 3], sl[lr][lc + 3]);
            float4 u = *reinterpret_cast<const float4*>(&Wo[(bn + lr) * D_MODEL + k0 + lc]);
            split2(u.x, wh[lr][lc], wl[lr][lc]);
            split2(u.y, wh[lr][lc + 1], wl[lr][lc + 1]);
            split2(u.z, wh[lr][lc + 2], wl[lr][lc + 2]);
            split2(u.w, wh[lr][lc + 3], wl[lr][lc + 3]);
        }
        __syncthreads();
#pragma unroll
        for (int kk = 0; kk < 16; kk += 8) {
            int mr = mtile * 16 + gr;
            unsigned ah[4], al[4];
            ah[0] = bits(sh[mr][kk + tig]);     al[0] = bits(sl[mr][kk + tig]);
            ah[1] = bits(sh[mr + 8][kk + tig]); al[1] = bits(sl[mr + 8][kk + tig]);
            ah[2] = bits(sh[mr][kk + tig + 4]);     al[2] = bits(sl[mr][kk + tig + 4]);
            ah[3] = bits(sh[mr + 8][kk + tig + 4]); al[3] = bits(sl[mr + 8][kk + tig + 4]);
#pragma unroll
            for (int ni = 0; ni < 4; ni++) {
                int nr = ntile * 32 + ni * 8 + gr;
                unsigned bh0 = bits(wh[nr][kk + tig]), bl0 = bits(wl[nr][kk + tig]);
                unsigned bh1 = bits(wh[nr][kk + tig + 4]), bl1 = bits(wl[nr][kk + tig + 4]);
                mma3(acc[ni], ah, al, bh0, bh1, bl0, bl1);
            }
        }
        __syncthreads();
    }
#pragma unroll
    for (int ni = 0; ni < 4; ni++) {
        int m = bm + mtile * 16 + gr;
        int n = bn + ntile * 32 + ni * 8 + 2 * tig;
        *reinterpret_cast<float2*>(&out[m * D_MODEL + n]) = make_float2(acc[ni][0], acc[ni][1]);
        *reinterpret_cast<float2*>(&out[(m + 8) * D_MODEL + n]) = make_float2(acc[ni][2], acc[ni][3]);
    }
}

// ---------------- launch ----------------
extern "C" void kernel_launch(void* const* d_in, const int* in_sizes, int n_in,
                              void* d_out, int out_size) {
    const float* s   = (const float*)d_in[0];
    const float* z   = (const float*)d_in[1];
    const float* Wq  = (const float*)d_in[2];
    const float* bq  = (const float*)d_in[3];
    const float* Wk  = (const float*)d_in[4];
    const float* Wv  = (const float*)d_in[5];
    const float* Wg  = (const float*)d_in[6];
    const float* Wo  = (const float*)d_in[7];
    const float* lnw = (const float*)d_in[8];
    const float* lnb = (const float*)d_in[9];
    const float* Wz  = (const float*)d_in[10];
    float* out = (float*)d_out;

    const int attn_smem = (16 * 36 + 2 * 64 * 36 + 16 * PSW + 16) * 4;
    cudaFuncSetAttribute(attn_kernel, cudaFuncAttributeMaxDynamicSharedMemorySize, attn_smem);
    const int bias_smem = (2 * 64 * 132 + 16 * 132 + 128) * 4;
    cudaFuncSetAttribute(bias_kernel, cudaFuncAttributeMaxDynamicSharedMemorySize, bias_smem);

    prep_kernel<<<1, 128>>>(Wz, lnw, lnb);
    proj_kernel<<<dim3(D_MODEL / 64, N_TOK / 64, 4), 256>>>(s, Wq, bq, Wk, Wv, Wg);
    bias_kernel<<<dim3(N_TOK / 64, N_TOK / BIAS_ITILES), 256, bias_smem>>>(z);
    attn_kernel<<<dim3(N_TOK / 16, NH), 256, attn_smem>>>();
    out_kernel<<<dim3(D_MODEL / 64, N_TOK / 64), 256>>>(Wo, out);
}

// round 10
// speedup vs baseline: 1.1482x; 1.0632x over previous
#include <cuda_runtime.h>
#include <math.h>

#define N_TOK 768
#define D_MODEL 512
#define CZ 128
#define NH 16
#define DH 32
#define LN_EPS 1e-5f
#define PSW 772  // 772 % 32 == 4 -> conflict-free phase-2 A-fragment LDS
#define BIAS_ITILES 8

// ---------------- scratch ----------------
__device__ float g_q[N_TOK * D_MODEL];
__device__ float g_k[N_TOK * D_MODEL];
__device__ float g_v[N_TOK * D_MODEL];
__device__ float g_g[N_TOK * D_MODEL];
__device__ float g_o[N_TOK * D_MODEL];
__device__ float g_logits[(size_t)NH * N_TOK * N_TOK];  // bias (read by attn)
__device__ float g_A[NH * CZ];
__device__ float g_SA[NH];
__device__ float g_CB[NH];

__device__ __forceinline__ unsigned f2tf32(float x) {
    unsigned r;
    asm("cvt.rna.tf32.f32 %0, %1;" : "=r"(r) : "f"(x));
    return r;
}
__device__ __forceinline__ unsigned bits(float x) { return __float_as_uint(x); }

__device__ __forceinline__ void split2(float x, float& hi, float& lo) {
    hi = __uint_as_float(f2tf32(x));
    lo = x - hi;
}

__device__ __forceinline__ void mma_tf32(float* d,
                                         unsigned a0, unsigned a1, unsigned a2, unsigned a3,
                                         unsigned b0, unsigned b1) {
    asm volatile(
        "mma.sync.aligned.m16n8k8.row.col.f32.tf32.tf32.f32 "
        "{%0,%1,%2,%3}, {%4,%5,%6,%7}, {%8,%9}, {%0,%1,%2,%3};"
        : "+f"(d[0]), "+f"(d[1]), "+f"(d[2]), "+f"(d[3])
        : "r"(a0), "r"(a1), "r"(a2), "r"(a3), "r"(b0), "r"(b1));
}

__device__ __forceinline__ void mma3(float* d, const unsigned* ah, const unsigned* al,
                                     unsigned bh0, unsigned bh1, unsigned bl0, unsigned bl1) {
    mma_tf32(d, ah[0], ah[1], ah[2], ah[3], bh0, bh1);
    mma_tf32(d, ah[0], ah[1], ah[2], ah[3], bl0, bl1);
    mma_tf32(d, al[0], al[1], al[2], al[3], bh0, bh1);
}

__device__ __forceinline__ void cp_async16(unsigned dst, const void* src) {
    asm volatile("cp.async.cg.shared.global [%0], [%1], 16;" :: "r"(dst), "l"(src));
}

// ---------------- K0: fold LN affine into Wz ----------------
__global__ void prep_kernel(const float* __restrict__ Wz,
                            const float* __restrict__ lnw,
                            const float* __restrict__ lnb) {
    __shared__ float red[8];
    int c = threadIdx.x;
    float wc = lnw[c], bc = lnb[c];
    for (int h = 0; h < NH; h++) {
        float wz = Wz[h * CZ + c];
        float a = wz * wc;
        g_A[h * CZ + c] = a;
        float sa = a, cb = wz * bc;
        for (int o = 16; o; o >>= 1) {
            sa += __shfl_down_sync(0xffffffffu, sa, o);
            cb += __shfl_down_sync(0xffffffffu, cb, o);
        }
        if ((c & 31) == 0) { red[c >> 5] = sa; red[4 + (c >> 5)] = cb; }
        __syncthreads();
        if (c == 0) {
            g_SA[h] = red[0] + red[1] + red[2] + red[3];
            g_CB[h] = red[4] + red[5] + red[6] + red[7];
        }
        __syncthreads();
    }
}

// ---------------- K1: projections, dual-plane 3xTF32, BM=BN=64 ----------------
__global__ void proj_kernel(const float* __restrict__ s,
                            const float* __restrict__ Wq, const float* __restrict__ bq,
                            const float* __restrict__ Wk, const float* __restrict__ Wv,
                            const float* __restrict__ Wg) {
    __shared__ float sh[64][20], sl[64][20], wh[64][20], wl[64][20];
    int w = blockIdx.z;
    const float* W = (w == 0) ? Wq : (w == 1) ? Wk : (w == 2) ? Wv : Wg;
    float* C = (w == 0) ? g_q : (w == 1) ? g_k : (w == 2) ? g_v : g_g;
    int bm = blockIdx.y * 64, bn = blockIdx.x * 64;
    int tid = threadIdx.x;
    int wid = tid >> 5, lane = tid & 31;
    int mtile = wid & 3, ntile = wid >> 2;
    int gr = lane >> 2, tig = lane & 3;
    int lr = tid >> 2, lc = (tid & 3) * 4;
    float acc[4][4] = {};

    for (int k0 = 0; k0 < D_MODEL; k0 += 16) {
        {
            float4 v = *reinterpret_cast<const float4*>(&s[(bm + lr) * D_MODEL + k0 + lc]);
            split2(v.x, sh[lr][lc], sl[lr][lc]);
            split2(v.y, sh[lr][lc + 1], sl[lr][lc + 1]);
            split2(v.z, sh[lr][lc + 2], sl[lr][lc + 2]);
            split2(v.w, sh[lr][lc + 3], sl[lr][lc + 3]);
            float4 u = *reinterpret_cast<const float4*>(&W[(bn + lr) * D_MODEL + k0 + lc]);
            split2(u.x, wh[lr][lc], wl[lr][lc]);
            split2(u.y, wh[lr][lc + 1], wl[lr][lc + 1]);
            split2(u.z, wh[lr][lc + 2], wl[lr][lc + 2]);
            split2(u.w, wh[lr][lc + 3], wl[lr][lc + 3]);
        }
        __syncthreads();
#pragma unroll
        for (int kk = 0; kk < 16; kk += 8) {
            int mr = mtile * 16 + gr;
            unsigned ah[4], al[4];
            ah[0] = bits(sh[mr][kk + tig]);     al[0] = bits(sl[mr][kk + tig]);
            ah[1] = bits(sh[mr + 8][kk + tig]); al[1] = bits(sl[mr + 8][kk + tig]);
            ah[2] = bits(sh[mr][kk + tig + 4]);     al[2] = bits(sl[mr][kk + tig + 4]);
            ah[3] = bits(sh[mr + 8][kk + tig + 4]); al[3] = bits(sl[mr + 8][kk + tig + 4]);
#pragma unroll
            for (int ni = 0; ni < 4; ni++) {
                int nr = ntile * 32 + ni * 8 + gr;
                unsigned bh0 = bits(wh[nr][kk + tig]), bl0 = bits(wl[nr][kk + tig]);
                unsigned bh1 = bits(wh[nr][kk + tig + 4]), bl1 = bits(wl[nr][kk + tig + 4]);
                mma3(acc[ni], ah, al, bh0, bh1, bl0, bl1);
            }
        }
        __syncthreads();
    }
#pragma unroll
    for (int ni = 0; ni < 4; ni++) {
        int m = bm + mtile * 16 + gr;
        int n = bn + ntile * 32 + ni * 8 + 2 * tig;
        float b0 = 0.f, b1 = 0.f;
        if (w == 0) { b0 = bq[n]; b1 = bq[n + 1]; }
        *reinterpret_cast<float2*>(&C[m * D_MODEL + n]) =
            make_float2(acc[ni][0] + b0, acc[ni][1] + b1);
        *reinterpret_cast<float2*>(&C[(m + 8) * D_MODEL + n]) =
            make_float2(acc[ni][2] + b0, acc[ni][3] + b1);
    }
}

// ---------------- K2: pair bias, double-buffered cp.async (proven) ----------------
__global__ void bias_kernel(const float* __restrict__ z) {
    extern __shared__ float bsm[];
    float* zbuf[2] = {bsm, bsm + 64 * 132};
    float* As = bsm + 2 * 64 * 132;
    float* mu_s = As + 16 * 132;
    float* rs_s = mu_s + 64;
    int j0 = blockIdx.x * 64;
    int ibase = blockIdx.y * BIAS_ITILES;
    int tid = threadIdx.x;

    for (int e = tid; e < 16 * 32; e += 256) {
        int h = e >> 5, c4 = (e & 31) * 4;
        float4 v = *reinterpret_cast<const float4*>(&g_A[h * CZ + c4]);
        *reinterpret_cast<float4*>(&As[h * 132 + c4]) = v;
    }
    {
        const float* zb = z + ((size_t)ibase * N_TOK + j0) * CZ;
        unsigned dst = (unsigned)__cvta_generic_to_shared(zbuf[0]);
#pragma unroll
        for (int it = 0; it < 8; it++) {
            int f4 = tid + it * 256;
            int r = f4 >> 5, c4 = f4 & 31;
            cp_async16(dst + (r * 132 + c4 * 4) * 4, zb + r * CZ + c4 * 4);
        }
        asm volatile("cp.async.commit_group;");
    }

    int w = tid >> 5, lane = tid & 31;
    int mtile = w & 3, ntile = w >> 2;
    int gr = lane >> 2, tig = lane & 3;

    for (int t = 0; t < BIAS_ITILES; t++) {
        float* cur = zbuf[t & 1];
        if (t + 1 < BIAS_ITILES) {
            const float* zb = z + ((size_t)(ibase + t + 1) * N_TOK + j0) * CZ;
            unsigned dst = (unsigned)__cvta_generic_to_shared(zbuf[(t + 1) & 1]);
#pragma unroll
            for (int it = 0; it < 8; it++) {
                int f4 = tid + it * 256;
                int r = f4 >> 5, c4 = f4 & 31;
                cp_async16(dst + (r * 132 + c4 * 4) * 4, zb + r * CZ + c4 * 4);
            }
            asm volatile("cp.async.commit_group;");
            asm volatile("cp.async.wait_group 1;");
        } else {
            asm volatile("cp.async.wait_group 0;");
        }
        __syncthreads();

        {
            int row = tid >> 2, sub = tid & 3;
            float sm = 0.f, sq = 0.f;
#pragma unroll
            for (int c4 = 0; c4 < 8; c4++) {
                float4 v = *reinterpret_cast<float4*>(&cur[row * 132 + (sub * 8 + c4) * 4]);
                sm += v.x + v.y + v.z + v.w;
                sq += v.x * v.x + v.y * v.y + v.z * v.z + v.w * v.w;
            }
            sm += __shfl_xor_sync(0xffffffffu, sm, 1);
            sm += __shfl_xor_sync(0xffffffffu, sm, 2);
            sq += __shfl_xor_sync(0xffffffffu, sq, 1);
            sq += __shfl_xor_sync(0xffffffffu, sq, 2);
            if (sub == 0) {
                float m = sm * (1.0f / CZ);
                float var = sq * (1.0f / CZ) - m * m;
                mu_s[row] = m;
                rs_s[row] = rsqrtf(var + LN_EPS);
            }
        }
        __syncthreads();

        const float* zr0 = &cur[(mtile * 16 + gr) * 132];
        const float* zr1 = &cur[(mtile * 16 + gr + 8) * 132];
        const float* ar = &As[(ntile * 8 + gr) * 132];

        float d[4] = {};
#pragma unroll
        for (int k0 = 0; k0 < CZ; k0 += 8) {
            unsigned a0 = f2tf32(zr0[k0 + tig]);
            unsigned a1 = f2tf32(zr1[k0 + tig]);
            unsigned a2 = f2tf32(zr0[k0 + tig + 4]);
            unsigned a3 = f2tf32(zr1[k0 + tig + 4]);
            unsigned b0 = f2tf32(ar[k0 + tig]);
            unsigned b1 = f2tf32(ar[k0 + tig + 4]);
            mma_tf32(d, a0, a1, a2, a3, b0, b1);
        }

        int i = ibase + t;
        int jl = mtile * 16 + gr;
        int jh = jl + 8;
        int h0 = ntile * 8 + 2 * tig, h1 = h0 + 1;
        float mu_l = mu_s[jl], rs_l = rs_s[jl];
        float mu_h = mu_s[jh], rs_h = rs_s[jh];
        float sa0 = g_SA[h0], cb0 = g_CB[h0];
        float sa1 = g_SA[h1], cb1 = g_CB[h1];
        g_logits[((size_t)h0 * N_TOK + i) * N_TOK + j0 + jl] = rs_l * (d[0] - mu_l * sa0) + cb0;
        g_logits[((size_t)h1 * N_TOK + i) * N_TOK + j0 + jl] = rs_l * (d[1] - mu_l * sa1) + cb1;
        g_logits[((size_t)h0 * N_TOK + i) * N_TOK + j0 + jh] = rs_h * (d[2] - mu_h * sa0) + cb0;
        g_logits[((size_t)h1 * N_TOK + i) * N_TOK + j0 + jh] = rs_h * (d[3] - mu_h * sa1) + cb1;
        __syncthreads();
    }
}

// ---------------- K3: fused attention, sync-free phases, gmem fragments ----------------
// block = (16 q-rows, head), 256 thr = 8 warps. Warp w owns j in [96w, 96w+96).
// Phase 1: QK (3xTF32, B-frags straight from gmem K) + bias -> Ps (smem). No syncs.
// Softmax: exp in Ps, 1/sum in inv_s. One sync each side.
// Phase 2: P@V split-k by warp (V frags straight from gmem), smem reduction.
__global__ __launch_bounds__(256, 3) void attn_kernel() {
    extern __shared__ float sm_[];
    float* Ps = sm_;                     // [16][PSW]
    float* inv_s = Ps + 16 * PSW;        // [16]
    float* red = inv_s + 16;             // [8][512]
    int h = blockIdx.y;
    int i0 = blockIdx.x * 16;
    int tid = threadIdx.x;
    int wid = tid >> 5, lane = tid & 31;
    int gr = lane >> 2, tig = lane & 3;
    const float scale = 0.17677669529663687f;

    // Q A-fragments straight from gmem (scaled, dual-plane)
    unsigned qa_h[4][4], qa_l[4][4];
    {
        const float* qb = g_q + (size_t)i0 * D_MODEL + h * DH;
#pragma unroll
        for (int kk4 = 0; kk4 < 4; kk4++) {
            int k = kk4 * 8;
            float hi, lo;
            split2(qb[gr * D_MODEL + k + tig] * scale, hi, lo);
            qa_h[kk4][0] = bits(hi); qa_l[kk4][0] = bits(lo);
            split2(qb[(gr + 8) * D_MODEL + k + tig] * scale, hi, lo);
            qa_h[kk4][1] = bits(hi); qa_l[kk4][1] = bits(lo);
            split2(qb[gr * D_MODEL + k + tig + 4] * scale, hi, lo);
            qa_h[kk4][2] = bits(hi); qa_l[kk4][2] = bits(lo);
            split2(qb[(gr + 8) * D_MODEL + k + tig + 4] * scale, hi, lo);
            qa_h[kk4][3] = bits(hi); qa_l[kk4][3] = bits(lo);
        }
    }

    // ---- Phase 1: logits + bias -> Ps (sync-free; warps own disjoint columns) ----
    int jw = wid * 96;
    {
        const float* kb = g_k + h * DH;
        const float* bb = g_logits + ((size_t)h * N_TOK + i0) * N_TOK;
#pragma unroll
        for (int f = 0; f < 12; f++) {
            int n0 = jw + f * 8;
            float acc[4] = {};
#pragma unroll
            for (int kk4 = 0; kk4 < 4; kk4++) {
                int k = kk4 * 8;
                float hi, lo;
                float b0f = kb[(n0 + gr) * D_MODEL + k + tig];
                float b1f = kb[(n0 + gr) * D_MODEL + k + tig + 4];
                unsigned bh0, bl0, bh1, bl1;
                split2(b0f, hi, lo); bh0 = bits(hi); bl0 = bits(lo);
                split2(b1f, hi, lo); bh1 = bits(hi); bl1 = bits(lo);
                mma3(acc, qa_h[kk4], qa_l[kk4], bh0, bh1, bl0, bl1);
            }
            int jc = n0 + 2 * tig;
            float2 b0 = *reinterpret_cast<const float2*>(&bb[gr * N_TOK + jc]);
            float2 b1 = *reinterpret_cast<const float2*>(&bb[(gr + 8) * N_TOK + jc]);
            *reinterpret_cast<float2*>(&Ps[gr * PSW + jc]) =
                make_float2(acc[0] + b0.x, acc[1] + b0.y);
            *reinterpret_cast<float2*>(&Ps[(gr + 8) * PSW + jc]) =
                make_float2(acc[2] + b1.x, acc[3] + b1.y);
        }
    }
    __syncthreads();

    // ---- Softmax: exp stays in Ps, 1/sum -> inv_s ----
#pragma unroll
    for (int rr = 0; rr < 2; rr++) {
        int r = wid * 2 + rr;
        float v[24];
        float mx = -1e30f;
#pragma unroll
        for (int t = 0; t < 24; t++) {
            v[t] = Ps[r * PSW + lane + 32 * t];
            mx = fmaxf(mx, v[t]);
        }
#pragma unroll
        for (int o = 16; o; o >>= 1) mx = fmaxf(mx, __shfl_xor_sync(0xffffffffu, mx, o));
        float sum = 0.f;
#pragma unroll
        for (int t = 0; t < 24; t++) { v[t] = __expf(v[t] - mx); sum += v[t]; }
#pragma unroll
        for (int o = 16; o; o >>= 1) sum += __shfl_xor_sync(0xffffffffu, sum, o);
        if (lane == 0) inv_s[r] = 1.0f / sum;
#pragma unroll
        for (int t = 0; t < 24; t++) Ps[r * PSW + lane + 32 * t] = v[t];
    }
    __syncthreads();

    // ---- Phase 2: O = P @ V, split-k (warp w: j in [96w, 96w+96)), V frags from gmem ----
    float acc2[4][4] = {};
    {
        const float* vb = g_v + h * DH;
#pragma unroll
        for (int kk = 0; kk < 96; kk += 8) {
            int kg = jw + kk;
            unsigned ah[4], al[4];
            float hi, lo;
            split2(Ps[gr * PSW + kg + tig], hi, lo);           ah[0] = bits(hi); al[0] = bits(lo);
            split2(Ps[(gr + 8) * PSW + kg + tig], hi, lo);     ah[1] = bits(hi); al[1] = bits(lo);
            split2(Ps[gr * PSW + kg + tig + 4], hi, lo);       ah[2] = bits(hi); al[2] = bits(lo);
            split2(Ps[(gr + 8) * PSW + kg + tig + 4], hi, lo); ah[3] = bits(hi); al[3] = bits(lo);
#pragma unroll
            for (int ni = 0; ni < 4; ni++) {
                float b0f = vb[(kg + tig) * D_MODEL + ni * 8 + gr];
                float b1f = vb[(kg + tig + 4) * D_MODEL + ni * 8 + gr];
                unsigned bh0, bl0, bh1, bl1;
                split2(b0f, hi, lo); bh0 = bits(hi); bl0 = bits(lo);
                split2(b1f, hi, lo); bh1 = bits(hi); bl1 = bits(lo);
                mma3(acc2[ni], ah, al, bh0, bh1, bl0, bl1);
            }
        }
    }
    // stage partials
#pragma unroll
    for (int ni = 0; ni < 4; ni++) {
        *reinterpret_cast<float2*>(&red[wid * 512 + gr * 32 + ni * 8 + 2 * tig]) =
            make_float2(acc2[ni][0], acc2[ni][1]);
        *reinterpret_cast<float2*>(&red[wid * 512 + (gr + 8) * 32 + ni * 8 + 2 * tig]) =
            make_float2(acc2[ni][2], acc2[ni][3]);
    }
    __syncthreads();
    // final reduce: each thread owns 2 outputs
    {
        int e0 = tid * 2;
        int i = e0 >> 5, d = e0 & 31;
        float sx = 0.f, sy = 0.f;
#pragma unroll
        for (int w = 0; w < 8; w++) {
            float2 p = *reinterpret_cast<float2*>(&red[w * 512 + e0]);
            sx += p.x; sy += p.y;
        }
        float iv = inv_s[i];
        *reinterpret_cast<float2*>(&g_o[(size_t)(i0 + i) * D_MODEL + h * DH + d]) =
            make_float2(sx * iv, sy * iv);
    }
}

// ---------------- K4: out = (o * sigmoid(g)) @ Wo^T, dual-plane, BM=BN=64 ----------------
__global__ void out_kernel(const float* __restrict__ Wo, float* __restrict__ out) {
    __shared__ float sh[64][20], sl[64][20], wh[64][20], wl[64][20];
    int bm = blockIdx.y * 64, bn = blockIdx.x * 64;
    int tid = threadIdx.x;
    int wid = tid >> 5, lane = tid & 31;
    int mtile = wid & 3, ntile = wid >> 2;
    int gr = lane >> 2, tig = lane & 3;
    int lr = tid >> 2, lc = (tid & 3) * 4;
    float acc[4][4] = {};

    for (int k0 = 0; k0 < D_MODEL; k0 += 16) {
        {
            float4 va = *reinterpret_cast<const float4*>(&g_o[(bm + lr) * D_MODEL + k0 + lc]);
            float4 vg = *reinterpret_cast<const float4*>(&g_g[(bm + lr) * D_MODEL + k0 + lc]);
            va.x *= 1.0f / (1.0f + __expf(-vg.x));
            va.y *= 1.0f / (1.0f + __expf(-vg.y));
            va.z *= 1.0f / (1.0f + __expf(-vg.z));
            va.w *= 1.0f / (1.0f + __expf(-vg.w));
            split2(va.x, sh[lr][lc], sl[lr][lc]);
            split2(va.y, sh[lr][lc + 1], sl[lr][lc + 1]);
            split2(va.z, sh[lr][lc + 2], sl[lr][lc + 2]);
            split2(va.w, sh[lr][lc + 3], sl[lr][lc + 3]);
            float4 u = *reinterpret_cast<const float4*>(&Wo[(bn + lr) * D_MODEL + k0 + lc]);
            split2(u.x, wh[lr][lc], wl[lr][lc]);
            split2(u.y, wh[lr][lc + 1], wl[lr][lc + 1]);
            split2(u.z, wh[lr][lc + 2], wl[lr][lc + 2]);
            split2(u.w, wh[lr][lc + 3], wl[lr][lc + 3]);
        }
        __syncthreads();
#pragma unroll
        for (int kk = 0; kk < 16; kk += 8) {
            int mr = mtile * 16 + gr;
            unsigned ah[4], al[4];
            ah[0] = bits(sh[mr][kk + tig]);     al[0] = bits(sl[mr][kk + tig]);
            ah[1] = bits(sh[mr + 8][kk + tig]); al[1] = bits(sl[mr + 8][kk + tig]);
            ah[2] = bits(sh[mr][kk + tig + 4]);     al[2] = bits(sl[mr][kk + tig + 4]);
            ah[3] = bits(sh[mr + 8][kk + tig + 4]); al[3] = bits(sl[mr + 8][kk + tig + 4]);
#pragma unroll
            for (int ni = 0; ni < 4; ni++) {
                int nr = ntile * 32 + ni * 8 + gr;
                unsigned bh0 = bits(wh[nr][kk + tig]), bl0 = bits(wl[nr][kk + tig]);
                unsigned bh1 = bits(wh[nr][kk + tig + 4]), bl1 = bits(wl[nr][kk + tig + 4]);
                mma3(acc[ni], ah, al, bh0, bh1, bl0, bl1);
            }
        }
        __syncthreads();
    }
#pragma unroll
    for (int ni = 0; ni < 4; ni++) {
        int m = bm + mtile * 16 + gr;
        int n = bn + ntile * 32 + ni * 8 + 2 * tig;
        *reinterpret_cast<float2*>(&out[m * D_MODEL + n]) = make_float2(acc[ni][0], acc[ni][1]);
        *reinterpret_cast<float2*>(&out[(m + 8) * D_MODEL + n]) = make_float2(acc[ni][2], acc[ni][3]);
    }
}

// ---------------- launch ----------------
extern "C" void kernel_launch(void* const* d_in, const int* in_sizes, int n_in,
                              void* d_out, int out_size) {
    const float* s   = (const float*)d_in[0];
    const float* z   = (const float*)d_in[1];
    const float* Wq  = (const float*)d_in[2];
    const float* bq  = (const float*)d_in[3];
    const float* Wk  = (const float*)d_in[4];
    const float* Wv  = (const float*)d_in[5];
    const float* Wg  = (const float*)d_in[6];
    const float* Wo  = (const float*)d_in[7];
    const float* lnw = (const float*)d_in[8];
    const float* lnb = (const float*)d_in[9];
    const float* Wz  = (const float*)d_in[10];
    float* out = (float*)d_out;

    const int attn_smem = (16 * PSW + 16 + 8 * 512) * 4;
    cudaFuncSetAttribute(attn_kernel, cudaFuncAttributeMaxDynamicSharedMemorySize, attn_smem);
    const int bias_smem = (2 * 64 * 132 + 16 * 132 + 128) * 4;
    cudaFuncSetAttribute(bias_kernel, cudaFuncAttributeMaxDynamicSharedMemorySize, bias_smem);

    prep_kernel<<<1, 128>>>(Wz, lnw, lnb);
    proj_kernel<<<dim3(D_MODEL / 64, N_TOK / 64, 4), 256>>>(s, Wq, bq, Wk, Wv, Wg);
    bias_kernel<<<dim3(N_TOK / 64, N_TOK / BIAS_ITILES), 256, bias_smem>>>(z);
    attn_kernel<<<dim3(N_TOK / 16, NH), 256, attn_smem>>>();
    out_kernel<<<dim3(D_MODEL / 64, N_TOK / 64), 256>>>(Wo, out);
}